// round 4
// baseline (speedup 1.0000x reference)
#include <cuda_runtime.h>
#include <cstddef>

// ---------------- problem constants ----------------
#define BB   2
#define CINX 64
#define CH   128
#define HH   64
#define WW   1024
#define HWX  (HH*WW)          // 65536
#define H2X  32
#define W2X  512
#define NP2  (H2X*W2X)        // 16384
#define RESB_ELEMS (BB*CH*NP2)   // 4194304

// ---------------- scratch (static device memory; no allocation) ----------------
__device__ float g_resA1[BB*CH*HWX];
__device__ float g_resA2[BB*CH*HWX];
__device__ float g_resA3[BB*CH*HWX];
__device__ float g_buf1 [BB*CH*HWX];
__device__ float g_buf2 [BB*CH*HWX];
__device__ float g_hT   [BB*HWX*CH];          // transposed h: [B][H][W][C]
__device__ float g_wn   [BB*NP2*25*16];       // [B*NP2][25][16]
__device__ float g_y    [(size_t)BB*NP2*2048];// pixel-major: [B*NP2][2048]

__device__ __forceinline__ float lrelu01(float z) { return z > 0.f ? z : 0.01f*z; }

// =====================================================================
// Direct conv, 128 out channels, output tile = 64 px (one row), bn(lrelu(conv+b))
// =====================================================================
template<int CIN, int KS, int DIL, int PAD>
__global__ __launch_bounds__(256)
void conv_lrelu_bn_k(const float* __restrict__ in, const float* __restrict__ wg,
                     const float* __restrict__ bias, const float* __restrict__ bns,
                     const float* __restrict__ bnb, float* __restrict__ out)
{
    constexpr int CC = 8, WT = 64, KK = KS*KS, HALO = (KS-1)*DIL, IW = WT + HALO;
    __shared__ float in_s[CC][KS][IW];
    __shared__ float w_s[CC][KK][128];
    const int w0 = blockIdx.x * WT;
    const int h  = blockIdx.y;
    const int b  = blockIdx.z;
    const int tid = threadIdx.x;
    const int ty = tid >> 4, tx = tid & 15;

    float acc[8][4];
    #pragma unroll
    for (int i = 0; i < 8; i++)
        #pragma unroll
        for (int p = 0; p < 4; p++) acc[i][p] = 0.f;

    for (int cb = 0; cb < CIN; cb += CC) {
        // input tile (zero-padded)
        for (int idx = tid; idx < CC*KS*IW; idx += 256) {
            int ci = idx / (KS*IW);
            int rem = idx - ci*(KS*IW);
            int r = rem / IW, col = rem - r*IW;
            int gy = h - PAD + r*DIL;
            int gx = w0 - PAD + col;
            float v = 0.f;
            if ((unsigned)gy < (unsigned)HH && (unsigned)gx < (unsigned)WW)
                v = in[((b*CIN + cb + ci)*HH + gy)*WW + gx];
            in_s[ci][r][col] = v;
        }
        // weights, coalesced gmem read, transposed smem store w_s[ci][k][oc]
        constexpr int WPO = CC*KK;
        for (int idx = tid*4; idx < 128*WPO; idx += 1024) {
            int oc = idx / WPO;
            int r  = idx - oc*WPO;
            float4 v = *reinterpret_cast<const float4*>(&wg[(oc*CIN + cb)*KK + r]);
            float vv[4] = {v.x, v.y, v.z, v.w};
            #pragma unroll
            for (int j = 0; j < 4; j++) {
                int rr = r + j;
                w_s[rr/KK][rr - (rr/KK)*KK][oc] = vv[j];
            }
        }
        __syncthreads();
        #pragma unroll
        for (int ci = 0; ci < CC; ci++) {
            #pragma unroll
            for (int kh = 0; kh < KS; kh++) {
                #pragma unroll
                for (int kw = 0; kw < KS; kw++) {
                    float wv[8];
                    *reinterpret_cast<float4*>(&wv[0]) =
                        *reinterpret_cast<const float4*>(&w_s[ci][kh*KS+kw][ty*8]);
                    *reinterpret_cast<float4*>(&wv[4]) =
                        *reinterpret_cast<const float4*>(&w_s[ci][kh*KS+kw][ty*8+4]);
                    float xv[4];
                    #pragma unroll
                    for (int p = 0; p < 4; p++) xv[p] = in_s[ci][kh][tx*4 + p + kw*DIL];
                    #pragma unroll
                    for (int i = 0; i < 8; i++)
                        #pragma unroll
                        for (int p = 0; p < 4; p++)
                            acc[i][p] += wv[i]*xv[p];
                }
            }
        }
        __syncthreads();
    }
    #pragma unroll
    for (int i = 0; i < 8; i++) {
        int oc = ty*8 + i;
        float bi = bias[oc], s = bns[oc], bb2 = bnb[oc];
        float zt[4];
        #pragma unroll
        for (int p = 0; p < 4; p++) zt[p] = s*lrelu01(acc[i][p] + bi) + bb2;
        *reinterpret_cast<float4*>(&out[((b*128 + oc)*HH + h)*WW + w0 + tx*4]) =
            make_float4(zt[0], zt[1], zt[2], zt[3]);
    }
}

// =====================================================================
// GEMM-step macro used by all pointwise kernels (16-K chunk, 8x4 tile)
// =====================================================================
#define GEMM_CHUNK_COMPUTE(ACC)                                               \
    _Pragma("unroll")                                                          \
    for (int kk = 0; kk < 16; kk++) {                                          \
        float wv[8];                                                           \
        *reinterpret_cast<float4*>(&wv[0]) =                                   \
            *reinterpret_cast<const float4*>(&w_s[kk][ty*8]);                  \
        *reinterpret_cast<float4*>(&wv[4]) =                                   \
            *reinterpret_cast<const float4*>(&w_s[kk][ty*8+4]);                \
        float xv[4];                                                           \
        *reinterpret_cast<float4*>(&xv[0]) =                                   \
            *reinterpret_cast<const float4*>(&in_s[kk][tx*4]);                 \
        _Pragma("unroll")                                                      \
        for (int i = 0; i < 8; i++)                                            \
            _Pragma("unroll")                                                  \
            for (int p = 0; p < 4; p++) ACC[i][p] += wv[i]*xv[p];              \
    }

// =====================================================================
// Pointwise 128->128, NCHW in, relu(bn(Wx+b)). TR=1 writes transposed [pix][C].
// =====================================================================
template<int TR>
__global__ __launch_bounds__(256)
void gemm128_relu_bn_k(const float* __restrict__ in, const float* __restrict__ wg,
                       const float* __restrict__ bias, const float* __restrict__ bns,
                       const float* __restrict__ bnb, float* __restrict__ out)
{
    __shared__ float in_s[16][64];
    __shared__ float w_s[16][128];
    __shared__ float o_s[TR ? 128*65 : 1];
    const int gp = blockIdx.x * 64;
    const int b = gp / HWX, pp = gp - b*HWX;
    const int tid = threadIdx.x, ty = tid >> 4, tx = tid & 15;
    float acc[8][4];
    #pragma unroll
    for (int i = 0; i < 8; i++)
        #pragma unroll
        for (int p = 0; p < 4; p++) acc[i][p] = 0.f;

    for (int kc = 0; kc < 8; kc++) {
        { int ch = tid >> 4, seg = tid & 15;
          *reinterpret_cast<float4*>(&in_s[ch][seg*4]) =
              *reinterpret_cast<const float4*>(&in[((b*128 + kc*16 + ch)*HWX) + pp + seg*4]); }
        for (int t2 = tid; t2 < 512; t2 += 256) {
            int oc = t2 >> 2, q = t2 & 3;
            float4 v = *reinterpret_cast<const float4*>(&wg[oc*128 + kc*16 + q*4]);
            w_s[q*4+0][oc] = v.x; w_s[q*4+1][oc] = v.y;
            w_s[q*4+2][oc] = v.z; w_s[q*4+3][oc] = v.w;
        }
        __syncthreads();
        GEMM_CHUNK_COMPUTE(acc)
        __syncthreads();
    }
    if (TR == 0) {
        #pragma unroll
        for (int i = 0; i < 8; i++) {
            int oc = ty*8 + i;
            float bi = bias[oc], s = bns[oc], bb2 = bnb[oc];
            float zt[4];
            #pragma unroll
            for (int p = 0; p < 4; p++) {
                float z = s*(acc[i][p] + bi) + bb2;
                zt[p] = z > 0.f ? z : 0.f;
            }
            *reinterpret_cast<float4*>(&out[((b*128 + oc)*HWX) + pp + tx*4]) =
                make_float4(zt[0], zt[1], zt[2], zt[3]);
        }
    } else {
        #pragma unroll
        for (int i = 0; i < 8; i++) {
            int oc = ty*8 + i;
            float bi = bias[oc], s = bns[oc], bb2 = bnb[oc];
            #pragma unroll
            for (int p = 0; p < 4; p++) {
                float z = s*(acc[i][p] + bi) + bb2;
                o_s[oc*65 + tx*4 + p] = z > 0.f ? z : 0.f;
            }
        }
        __syncthreads();
        for (int idx = tid; idx < 8192; idx += 256) {
            int oc = idx & 127, pix = idx >> 7;
            out[((size_t)(b*HWX + pp + pix))*128 + oc] = o_s[oc*65 + pix];
        }
    }
}

// =====================================================================
// resA: bn3(lrelu(c5 @ concat + c5_b)) + lrelu(c1 @ x + c1_b)
// =====================================================================
__global__ __launch_bounds__(256)
void resa_gemm_k(const float* __restrict__ r1, const float* __restrict__ r2,
                 const float* __restrict__ r3, const float* __restrict__ x,
                 const float* __restrict__ c5w, const float* __restrict__ c5b,
                 const float* __restrict__ c1w, const float* __restrict__ c1b,
                 const float* __restrict__ bns, const float* __restrict__ bnb,
                 float* __restrict__ out)
{
    __shared__ float in_s[16][64];
    __shared__ float w_s[16][128];
    const int gp = blockIdx.x * 64;
    const int b = gp / HWX, pp = gp - b*HWX;
    const int tid = threadIdx.x, ty = tid >> 4, tx = tid & 15;
    float acc[8][4], acc2[8][4];
    #pragma unroll
    for (int i = 0; i < 8; i++)
        #pragma unroll
        for (int p = 0; p < 4; p++) { acc[i][p] = 0.f; acc2[i][p] = 0.f; }

    for (int kc = 0; kc < 24; kc++) {
        const float* src = kc < 8 ? r1 : (kc < 16 ? r2 : r3);
        int chb = (kc & 7)*16;
        { int ch = tid >> 4, seg = tid & 15;
          *reinterpret_cast<float4*>(&in_s[ch][seg*4]) =
              *reinterpret_cast<const float4*>(&src[((b*128 + chb + ch)*HWX) + pp + seg*4]); }
        for (int t2 = tid; t2 < 512; t2 += 256) {
            int oc = t2 >> 2, q = t2 & 3;
            float4 v = *reinterpret_cast<const float4*>(&c5w[oc*384 + kc*16 + q*4]);
            w_s[q*4+0][oc] = v.x; w_s[q*4+1][oc] = v.y;
            w_s[q*4+2][oc] = v.z; w_s[q*4+3][oc] = v.w;
        }
        __syncthreads();
        GEMM_CHUNK_COMPUTE(acc)
        __syncthreads();
    }
    for (int kc = 0; kc < 4; kc++) {
        { int ch = tid >> 4, seg = tid & 15;
          *reinterpret_cast<float4*>(&in_s[ch][seg*4]) =
              *reinterpret_cast<const float4*>(&x[((b*64 + kc*16 + ch)*HWX) + pp + seg*4]); }
        for (int t2 = tid; t2 < 512; t2 += 256) {
            int oc = t2 >> 2, q = t2 & 3;
            float4 v = *reinterpret_cast<const float4*>(&c1w[oc*64 + kc*16 + q*4]);
            w_s[q*4+0][oc] = v.x; w_s[q*4+1][oc] = v.y;
            w_s[q*4+2][oc] = v.z; w_s[q*4+3][oc] = v.w;
        }
        __syncthreads();
        GEMM_CHUNK_COMPUTE(acc2)
        __syncthreads();
    }
    #pragma unroll
    for (int i = 0; i < 8; i++) {
        int oc = ty*8 + i;
        float b5 = c5b[oc], b1 = c1b[oc], s = bns[oc], bb2 = bnb[oc];
        float zt[4];
        #pragma unroll
        for (int p = 0; p < 4; p++)
            zt[p] = s*lrelu01(acc[i][p] + b5) + bb2 + lrelu01(acc2[i][p] + b1);
        *reinterpret_cast<float4*>(&out[((b*128 + oc)*HWX) + pp + tx*4]) =
            make_float4(zt[0], zt[1], zt[2], zt[3]);
    }
}

// =====================================================================
// WeightNet: gxyz -> 8 -> 8 -> 16, per (b, k, pixel)
// =====================================================================
__global__ __launch_bounds__(256)
void weightnet_k(const float* __restrict__ xyz,
                 const float* __restrict__ w1w, const float* __restrict__ w1b,
                 const float* __restrict__ w2w, const float* __restrict__ w2b,
                 const float* __restrict__ w3w, const float* __restrict__ w3b,
                 const float* __restrict__ s1, const float* __restrict__ b1,
                 const float* __restrict__ s2, const float* __restrict__ b2,
                 const float* __restrict__ s3, const float* __restrict__ b3,
                 float* __restrict__ out)
{
    int g = blockIdx.x*256 + threadIdx.x;   // B*25*NP2 = 819200
    int pix = g & (NP2 - 1);
    int rest = g >> 14;
    int k = rest % 25, b = rest / 25;
    int h2 = pix >> 9, w2 = pix & 511;
    int hi = 2*h2 - 2 + k/5, wi = 2*w2 - 2 + (k % 5);
    bool inb = ((unsigned)hi < (unsigned)HH) && ((unsigned)wi < (unsigned)WW);
    float gv[3];
    #pragma unroll
    for (int c = 0; c < 3; c++) {
        float ctr = xyz[(b*3 + c)*HWX + (2*h2)*WW + 2*w2];
        float nb  = inb ? xyz[(b*3 + c)*HWX + hi*WW + wi] : 0.f;
        gv[c] = nb - ctr;
    }
    float a1[8];
    #pragma unroll
    for (int j = 0; j < 8; j++) {
        float z = w1b[j];
        #pragma unroll
        for (int c = 0; c < 3; c++) z += w1w[j*3 + c]*gv[c];
        z = s1[j]*z + b1[j];
        a1[j] = z > 0.f ? z : 0.f;
    }
    float a2[8];
    #pragma unroll
    for (int j = 0; j < 8; j++) {
        float z = w2b[j];
        #pragma unroll
        for (int i = 0; i < 8; i++) z += w2w[j*8 + i]*a1[i];
        z = s2[j]*z + b2[j];
        a2[j] = z > 0.f ? z : 0.f;
    }
    float o[16];
    #pragma unroll
    for (int n = 0; n < 16; n++) {
        float z = w3b[n];
        #pragma unroll
        for (int i = 0; i < 8; i++) z += w3w[n*8 + i]*a2[i];
        z = s3[n]*z + b3[n];
        o[n] = z > 0.f ? z : 0.f;
    }
    size_t base = (((size_t)(b*NP2 + pix))*25 + k)*16;
    #pragma unroll
    for (int q = 0; q < 4; q++)
        *reinterpret_cast<float4*>(&out[base + q*4]) =
            make_float4(o[q*4], o[q*4+1], o[q*4+2], o[q*4+3]);
}

// =====================================================================
// Einsum: y[pix][c*16+n] = sum_k unf(hT)[c][k] * wn[pix][k][n], 2 pixels/block
// =====================================================================
__global__ __launch_bounds__(128)
void einsum_k(const float* __restrict__ hT, const float* __restrict__ wn,
              float* __restrict__ y)
{
    __shared__ float u_s[2][128][25];
    __shared__ float wn_s[2][400];
    const int gpix = blockIdx.x*2;
    const int b = gpix / NP2;
    const int tid = threadIdx.x;

    for (int i = tid; i < 800; i += 128) {
        int pl = i / 400, r = i - pl*400;
        wn_s[pl][r] = wn[(size_t)(gpix + pl)*400 + r];
    }
    for (int idx = 0; idx < 50; idx++) {
        int pl = idx / 25, k = idx - pl*25;
        int pp = (gpix + pl) - b*NP2;
        int h2 = pp >> 9, w2 = pp & 511;
        int hi = 2*h2 - 2 + k/5, wi = 2*w2 - 2 + (k % 5);
        float v = 0.f;
        if ((unsigned)hi < (unsigned)HH && (unsigned)wi < (unsigned)WW)
            v = hT[((size_t)(b*HH + hi)*WW + wi)*128 + tid];
        u_s[pl][tid][k] = v;
    }
    __syncthreads();

    const int s = tid & 63, pl = tid >> 6;
    const int cg = s & 15, ng = s >> 4;
    float acc[8][4];
    #pragma unroll
    for (int i = 0; i < 8; i++)
        #pragma unroll
        for (int n = 0; n < 4; n++) acc[i][n] = 0.f;

    #pragma unroll
    for (int k = 0; k < 25; k++) {
        float u[8];
        #pragma unroll
        for (int i = 0; i < 8; i++) u[i] = u_s[pl][cg*8 + i][k];
        float4 wv = *reinterpret_cast<const float4*>(&wn_s[pl][k*16 + ng*4]);
        float wvv[4] = {wv.x, wv.y, wv.z, wv.w};
        #pragma unroll
        for (int i = 0; i < 8; i++)
            #pragma unroll
            for (int n = 0; n < 4; n++) acc[i][n] += u[i]*wvv[n];
    }
    size_t base = (size_t)(gpix + pl)*2048;
    #pragma unroll
    for (int i = 0; i < 8; i++)
        *reinterpret_cast<float4*>(&y[base + (cg*8 + i)*16 + ng*4]) =
            make_float4(acc[i][0], acc[i][1], acc[i][2], acc[i][3]);
}

// =====================================================================
// Final GEMM: K=2048, y pixel-major in, resB NCHW out, relu(bn(.))
// =====================================================================
__global__ __launch_bounds__(256)
void final_gemm_k(const float* __restrict__ y, const float* __restrict__ lw,
                  const float* __restrict__ lb, const float* __restrict__ bns,
                  const float* __restrict__ bnb, float* __restrict__ out)
{
    __shared__ float in_s[16][64];
    __shared__ float w_s[16][128];
    const int gp = blockIdx.x * 64;          // over B*NP2
    const int b = gp / NP2, pp = gp - b*NP2;
    const int tid = threadIdx.x, ty = tid >> 4, tx = tid & 15;
    float acc[8][4];
    #pragma unroll
    for (int i = 0; i < 8; i++)
        #pragma unroll
        for (int p = 0; p < 4; p++) acc[i][p] = 0.f;

    for (int kc = 0; kc < 128; kc++) {
        { int pix = tid >> 2, q = tid & 3;
          float4 v = *reinterpret_cast<const float4*>(&y[(size_t)(gp + pix)*2048 + kc*16 + q*4]);
          in_s[q*4+0][pix] = v.x; in_s[q*4+1][pix] = v.y;
          in_s[q*4+2][pix] = v.z; in_s[q*4+3][pix] = v.w; }
        for (int t2 = tid; t2 < 512; t2 += 256) {
            int oc = t2 >> 2, q = t2 & 3;
            float4 v = *reinterpret_cast<const float4*>(&lw[oc*2048 + kc*16 + q*4]);
            w_s[q*4+0][oc] = v.x; w_s[q*4+1][oc] = v.y;
            w_s[q*4+2][oc] = v.z; w_s[q*4+3][oc] = v.w;
        }
        __syncthreads();
        GEMM_CHUNK_COMPUTE(acc)
        __syncthreads();
    }
    #pragma unroll
    for (int i = 0; i < 8; i++) {
        int oc = ty*8 + i;
        float bi = lb[oc], s = bns[oc], bb2 = bnb[oc];
        float zt[4];
        #pragma unroll
        for (int p = 0; p < 4; p++) {
            float z = s*(acc[i][p] + bi) + bb2;
            zt[p] = z > 0.f ? z : 0.f;
        }
        *reinterpret_cast<float4*>(&out[((b*128 + oc)*NP2) + pp + tx*4]) =
            make_float4(zt[0], zt[1], zt[2], zt[3]);
    }
}

// =====================================================================
// host launcher
// =====================================================================
extern "C" void kernel_launch(void* const* d_in, const int* in_sizes, int n_in,
                              void* d_out, int out_size)
{
    const float* x      = (const float*)d_in[0];
    const float* xyz    = (const float*)d_in[1];
    const float* c1_w   = (const float*)d_in[2];
    const float* c1_b   = (const float*)d_in[3];
    const float* c2_w   = (const float*)d_in[4];
    const float* c2_b   = (const float*)d_in[5];
    const float* c3_w   = (const float*)d_in[6];
    const float* c3_b   = (const float*)d_in[7];
    const float* c4_w   = (const float*)d_in[8];
    const float* c4_b   = (const float*)d_in[9];
    const float* c5_w   = (const float*)d_in[10];
    const float* c5_b   = (const float*)d_in[11];
    const float* rbn_s  = (const float*)d_in[12];
    const float* rbn_b  = (const float*)d_in[13];
    const float* p_w    = (const float*)d_in[14];
    const float* p_b    = (const float*)d_in[15];
    const float* pbn_s  = (const float*)d_in[16];
    const float* pbn_b  = (const float*)d_in[17];
    const float* lin_w  = (const float*)d_in[18];
    const float* lin_b  = (const float*)d_in[19];
    const float* w1_w   = (const float*)d_in[20];
    const float* w1_b   = (const float*)d_in[21];
    const float* w2_w   = (const float*)d_in[22];
    const float* w2_b   = (const float*)d_in[23];
    const float* w3_w   = (const float*)d_in[24];
    const float* w3_b   = (const float*)d_in[25];
    const float* wbn1_s = (const float*)d_in[26];
    const float* wbn1_b = (const float*)d_in[27];
    const float* wbn2_s = (const float*)d_in[28];
    const float* wbn2_b = (const float*)d_in[29];
    const float* wbn3_s = (const float*)d_in[30];
    const float* wbn3_b = (const float*)d_in[31];

    float* outp = (float*)d_out;
    float* resB = outp;                 // [B,128,H2,W2]
    float* resA = outp + RESB_ELEMS;    // [B,128,H,W]

    float *A1, *A2, *A3, *B1, *B2, *HT, *WN, *Y;
    cudaGetSymbolAddress((void**)&A1, g_resA1);
    cudaGetSymbolAddress((void**)&A2, g_resA2);
    cudaGetSymbolAddress((void**)&A3, g_resA3);
    cudaGetSymbolAddress((void**)&B1, g_buf1);
    cudaGetSymbolAddress((void**)&B2, g_buf2);
    cudaGetSymbolAddress((void**)&HT, g_hT);
    cudaGetSymbolAddress((void**)&WN, g_wn);
    cudaGetSymbolAddress((void**)&Y,  g_y);

    dim3 cgrid(WW/64, HH, BB);
    // ResBlock trunk
    conv_lrelu_bn_k<64, 3, 1, 1><<<cgrid, 256>>>(x,  c2_w, c2_b, rbn_s,       rbn_b,       A1);
    conv_lrelu_bn_k<128,3, 2, 2><<<cgrid, 256>>>(A1, c3_w, c3_b, rbn_s + 128, rbn_b + 128, A2);
    conv_lrelu_bn_k<128,2, 2, 1><<<cgrid, 256>>>(A2, c4_w, c4_b, rbn_s + 256, rbn_b + 256, A3);
    resa_gemm_k<<<BB*HWX/64, 256>>>(A1, A2, A3, x, c5_w, c5_b, c1_w, c1_b,
                                    rbn_s + 384, rbn_b + 384, resA);
    // Pointwise MLP (3rd layer writes transposed for the unfold gather)
    gemm128_relu_bn_k<0><<<BB*HWX/64, 256>>>(resA, p_w,          p_b,       pbn_s,       pbn_b,       B1);
    gemm128_relu_bn_k<0><<<BB*HWX/64, 256>>>(B1,   p_w + 16384,  p_b + 128, pbn_s + 128, pbn_b + 128, B2);
    gemm128_relu_bn_k<1><<<BB*HWX/64, 256>>>(B2,   p_w + 32768,  p_b + 256, pbn_s + 256, pbn_b + 256, HT);
    // WeightNet on geometry
    weightnet_k<<<(BB*25*NP2)/256, 256>>>(xyz, w1_w, w1_b, w2_w, w2_b, w3_w, w3_b,
                                          wbn1_s, wbn1_b, wbn2_s, wbn2_b, wbn3_s, wbn3_b, WN);
    // unfold x wn einsum -> y (pixel-major)
    einsum_k<<<BB*NP2/2, 128>>>(HT, WN, Y);
    // final 128x2048 pointwise GEMM -> resB
    final_gemm_k<<<BB*NP2/64, 256>>>(Y, lin_w, lin_b, pbn_s + 384, pbn_b + 384, resB);
}

// round 5
// speedup vs baseline: 1.1504x; 1.1504x over previous
#include <cuda_runtime.h>
#include <cstddef>

// ---------------- problem constants ----------------
#define BB   2
#define CINX 64
#define CH   128
#define HH   64
#define WW   1024
#define HWX  (HH*WW)          // 65536
#define H2X  32
#define W2X  512
#define NP2  (H2X*W2X)        // 16384
#define RESB_ELEMS (BB*CH*NP2)   // 4194304

typedef unsigned long long U64;

// f32x2 packed FMA (Blackwell): c = a*b + c elementwise on 2 packed fp32
#define FMA2(c, a, b) asm("fma.rn.f32x2 %0, %1, %2, %0;" : "+l"(c) : "l"(a), "l"(b))
#define PACK2(d, x)   asm("mov.b64 %0, {%1, %1};" : "=l"(d) : "r"(__float_as_uint(x)))
#define UNPK2(lo, hi, d) asm("mov.b64 {%0, %1}, %2;" : "=r"(lo), "=r"(hi) : "l"(d))

// ---------------- scratch (static device memory; no allocation) ----------------
__device__ float g_resA1[BB*CH*HWX];
__device__ float g_resA2[BB*CH*HWX];
__device__ float g_resA3[BB*CH*HWX];
__device__ float g_buf1 [BB*CH*HWX];
__device__ float g_buf2 [BB*CH*HWX];
__device__ float g_hT   [BB*HWX*CH];          // transposed h: [B][H][W][C]
__device__ float g_wn   [BB*NP2*25*16];       // [B*NP2][25][16]
__device__ float g_y    [(size_t)BB*NP2*2048];// pixel-major: [B*NP2][2048]

__device__ __forceinline__ float lrelu01(float z) { return z > 0.f ? z : 0.01f*z; }

// =====================================================================
// Shared GEMM inner: 16-K chunk, 4 oc-pair x 8 px per thread, f32x2
// in_s: [16][128] pixel-minor; w_s: [16][128] oc-minor
// =====================================================================
__device__ __forceinline__ void gemm_chunk_f2(const float* __restrict__ in_s,
                                              const float* __restrict__ w_s,
                                              int ty, int tx, U64 acc[4][8])
{
    #pragma unroll
    for (int kk = 0; kk < 16; kk++) {
        ulonglong2 wa = *reinterpret_cast<const ulonglong2*>(w_s + kk*128 + ty*8);
        ulonglong2 wb = *reinterpret_cast<const ulonglong2*>(w_s + kk*128 + ty*8 + 4);
        U64 wp[4] = {wa.x, wa.y, wb.x, wb.y};
        float4 xa = *reinterpret_cast<const float4*>(in_s + kk*128 + tx*8);
        float4 xb = *reinterpret_cast<const float4*>(in_s + kk*128 + tx*8 + 4);
        float xs[8] = {xa.x, xa.y, xa.z, xa.w, xb.x, xb.y, xb.z, xb.w};
        U64 xp[8];
        #pragma unroll
        for (int p = 0; p < 8; p++) PACK2(xp[p], xs[p]);
        #pragma unroll
        for (int j = 0; j < 4; j++)
            #pragma unroll
            for (int p = 0; p < 8; p++)
                FMA2(acc[j][p], wp[j], xp[p]);
    }
}

// =====================================================================
// Direct conv, 128 oc, 128-px output tile (one row), bn(lrelu(conv+b)), f32x2
// =====================================================================
template<int CIN, int KS, int DIL, int PAD>
__global__ __launch_bounds__(256)
void conv_f2_k(const float* __restrict__ in, const float* __restrict__ wg,
               const float* __restrict__ bias, const float* __restrict__ bns,
               const float* __restrict__ bnb, float* __restrict__ out)
{
    constexpr int CC = 4, WT = 128, KK = KS*KS, IWP = 136;
    __shared__ __align__(16) float in_s[CC*KS*IWP];
    __shared__ __align__(16) float w_s[CC*KK*128];
    const int w0 = blockIdx.x * WT;
    const int h  = blockIdx.y;
    const int b  = blockIdx.z;
    const int tid = threadIdx.x;
    const int ty = tid >> 4, tx = tid & 15;

    U64 acc[4][8];
    #pragma unroll
    for (int j = 0; j < 4; j++)
        #pragma unroll
        for (int p = 0; p < 8; p++) acc[j][p] = 0ULL;

    for (int cb = 0; cb < CIN; cb += CC) {
        // input tile (zero-padded), contiguous smem fill
        for (int idx = tid; idx < CC*KS*IWP; idx += 256) {
            int ci  = idx / (KS*IWP);
            int rem = idx - ci*(KS*IWP);
            int r = rem / IWP, col = rem - r*IWP;
            int gy = h - PAD + r*DIL;
            int gx = w0 - PAD + col;
            float v = 0.f;
            if ((unsigned)gy < (unsigned)HH && (unsigned)gx < (unsigned)WW)
                v = in[((b*CIN + cb + ci)*HH + gy)*WW + gx];
            in_s[idx] = v;
        }
        // weights transposed to w_s[(ci*KK+k)*128 + oc]
        constexpr int WPO = CC*KK;
        for (int idx = tid*4; idx < 128*WPO; idx += 1024) {
            int oc = idx / WPO;
            int r  = idx - oc*WPO;
            float4 v = *reinterpret_cast<const float4*>(&wg[(oc*CIN + cb)*KK + r]);
            float vv[4] = {v.x, v.y, v.z, v.w};
            #pragma unroll
            for (int jj = 0; jj < 4; jj++) {
                int rr = r + jj;
                int ci = rr / KK, k = rr - ci*KK;
                w_s[(ci*KK + k)*128 + oc] = vv[jj];
            }
        }
        __syncthreads();
        #pragma unroll
        for (int ci = 0; ci < CC; ci++) {
            #pragma unroll
            for (int kh = 0; kh < KS; kh++) {
                const float* xrow = in_s + (ci*KS + kh)*IWP + tx*8;
                float xr[12];
                *reinterpret_cast<float4*>(&xr[0]) = *reinterpret_cast<const float4*>(xrow);
                *reinterpret_cast<float4*>(&xr[4]) = *reinterpret_cast<const float4*>(xrow + 4);
                *reinterpret_cast<float4*>(&xr[8]) = *reinterpret_cast<const float4*>(xrow + 8);
                #pragma unroll
                for (int kw = 0; kw < KS; kw++) {
                    const float* wrow = w_s + (ci*KK + kh*KS + kw)*128 + ty*8;
                    ulonglong2 wa = *reinterpret_cast<const ulonglong2*>(wrow);
                    ulonglong2 wb = *reinterpret_cast<const ulonglong2*>(wrow + 4);
                    U64 wp[4] = {wa.x, wa.y, wb.x, wb.y};
                    U64 xp[8];
                    #pragma unroll
                    for (int p = 0; p < 8; p++) PACK2(xp[p], xr[p + kw*DIL]);
                    #pragma unroll
                    for (int j = 0; j < 4; j++)
                        #pragma unroll
                        for (int p = 0; p < 8; p++)
                            FMA2(acc[j][p], wp[j], xp[p]);
                }
            }
        }
        __syncthreads();
    }
    #pragma unroll
    for (int j = 0; j < 4; j++) {
        float lo[8], hi[8];
        #pragma unroll
        for (int p = 0; p < 8; p++) {
            unsigned a, c; UNPK2(a, c, acc[j][p]);
            lo[p] = __uint_as_float(a); hi[p] = __uint_as_float(c);
        }
        int oc0 = ty*8 + 2*j;
        #pragma unroll
        for (int hh2 = 0; hh2 < 2; hh2++) {
            int oc = oc0 + hh2;
            const float* src = hh2 ? hi : lo;
            float bi = bias[oc], s = bns[oc], bb2 = bnb[oc];
            float zt[8];
            #pragma unroll
            for (int p = 0; p < 8; p++) zt[p] = s*lrelu01(src[p] + bi) + bb2;
            float* op = &out[((b*128 + oc)*HH + h)*WW + w0 + tx*8];
            *reinterpret_cast<float4*>(op)     = make_float4(zt[0], zt[1], zt[2], zt[3]);
            *reinterpret_cast<float4*>(op + 4) = make_float4(zt[4], zt[5], zt[6], zt[7]);
        }
    }
}

// =====================================================================
// Pointwise 128->128, NCHW in, relu(bn(Wx+b)). TR=1 writes transposed [pix][C].
// 128 px per block.
// =====================================================================
template<int TR>
__global__ __launch_bounds__(256)
void gemm128_f2_k(const float* __restrict__ in, const float* __restrict__ wg,
                  const float* __restrict__ bias, const float* __restrict__ bns,
                  const float* __restrict__ bnb, float* __restrict__ out)
{
    __shared__ __align__(16) float sraw[4224];
    float* in_s = sraw;          // [16][128]
    float* w_s  = sraw + 2048;   // [16][128]
    const int gp = blockIdx.x * 128;
    const int b = gp / HWX, pp = gp - b*HWX;
    const int tid = threadIdx.x, ty = tid >> 4, tx = tid & 15;
    U64 acc[4][8];
    #pragma unroll
    for (int j = 0; j < 4; j++)
        #pragma unroll
        for (int p = 0; p < 8; p++) acc[j][p] = 0ULL;

    for (int kc = 0; kc < 8; kc++) {
        { int ch = ty, seg = tx;
          const float* sp = &in[((b*128 + kc*16 + ch)*HWX) + pp + seg*8];
          *reinterpret_cast<float4*>(&in_s[ch*128 + seg*8])     = *reinterpret_cast<const float4*>(sp);
          *reinterpret_cast<float4*>(&in_s[ch*128 + seg*8 + 4]) = *reinterpret_cast<const float4*>(sp + 4); }
        for (int t2 = tid; t2 < 512; t2 += 256) {
            int oc = t2 >> 2, q = t2 & 3;
            float4 v = *reinterpret_cast<const float4*>(&wg[oc*128 + kc*16 + q*4]);
            w_s[(q*4+0)*128 + oc] = v.x; w_s[(q*4+1)*128 + oc] = v.y;
            w_s[(q*4+2)*128 + oc] = v.z; w_s[(q*4+3)*128 + oc] = v.w;
        }
        __syncthreads();
        gemm_chunk_f2(in_s, w_s, ty, tx, acc);
        __syncthreads();
    }
    if (TR == 0) {
        #pragma unroll
        for (int j = 0; j < 4; j++) {
            float lo[8], hi[8];
            #pragma unroll
            for (int p = 0; p < 8; p++) {
                unsigned a, c; UNPK2(a, c, acc[j][p]);
                lo[p] = __uint_as_float(a); hi[p] = __uint_as_float(c);
            }
            int oc0 = ty*8 + 2*j;
            #pragma unroll
            for (int hh2 = 0; hh2 < 2; hh2++) {
                int oc = oc0 + hh2;
                const float* src = hh2 ? hi : lo;
                float bi = bias[oc], s = bns[oc], bb2 = bnb[oc];
                float zt[8];
                #pragma unroll
                for (int p = 0; p < 8; p++) {
                    float z = s*(src[p] + bi) + bb2;
                    zt[p] = z > 0.f ? z : 0.f;
                }
                float* op = &out[((b*128 + oc)*HWX) + pp + tx*8];
                *reinterpret_cast<float4*>(op)     = make_float4(zt[0], zt[1], zt[2], zt[3]);
                *reinterpret_cast<float4*>(op + 4) = make_float4(zt[4], zt[5], zt[6], zt[7]);
            }
        }
    } else {
        // 4-pass transpose via smem staging (reuses sraw)
        float* stage = sraw;   // [32][129]
        for (int g = 0; g < 4; g++) {
            __syncthreads();
            if ((ty >> 2) == g) {
                #pragma unroll
                for (int j = 0; j < 4; j++) {
                    unsigned a, c;
                    float lo[8], hi[8];
                    #pragma unroll
                    for (int p = 0; p < 8; p++) {
                        UNPK2(a, c, acc[j][p]);
                        lo[p] = __uint_as_float(a); hi[p] = __uint_as_float(c);
                    }
                    int oc = ty*8 + 2*j;             // global oc
                    int ocl = oc - g*32;             // local within group
                    float bi0 = bias[oc],   s0 = bns[oc],   b0 = bnb[oc];
                    float bi1 = bias[oc+1], s1 = bns[oc+1], b1 = bnb[oc+1];
                    #pragma unroll
                    for (int p = 0; p < 8; p++) {
                        float z0 = s0*(lo[p] + bi0) + b0;
                        float z1 = s1*(hi[p] + bi1) + b1;
                        stage[ocl*129 + tx*8 + p]     = z0 > 0.f ? z0 : 0.f;
                        stage[(ocl+1)*129 + tx*8 + p] = z1 > 0.f ? z1 : 0.f;
                    }
                }
            }
            __syncthreads();
            for (int t2 = tid; t2 < 1024; t2 += 256) {
                int pix = t2 >> 3, c4 = t2 & 7;
                float4 v;
                v.x = stage[(c4*4+0)*129 + pix];
                v.y = stage[(c4*4+1)*129 + pix];
                v.z = stage[(c4*4+2)*129 + pix];
                v.w = stage[(c4*4+3)*129 + pix];
                *reinterpret_cast<float4*>(&out[(size_t)(b*HWX + pp + pix)*128 + g*32 + c4*4]) = v;
            }
        }
    }
}

// =====================================================================
// resA: bn3(lrelu(c5 @ concat + c5_b)) + lrelu(c1 @ x + c1_b), f32x2
// =====================================================================
__global__ __launch_bounds__(256)
void resa_f2_k(const float* __restrict__ r1, const float* __restrict__ r2,
               const float* __restrict__ r3, const float* __restrict__ x,
               const float* __restrict__ c5w, const float* __restrict__ c5b,
               const float* __restrict__ c1w, const float* __restrict__ c1b,
               const float* __restrict__ bns, const float* __restrict__ bnb,
               float* __restrict__ out)
{
    __shared__ __align__(16) float sraw[4096];
    float* in_s = sraw;
    float* w_s  = sraw + 2048;
    const int gp = blockIdx.x * 128;
    const int b = gp / HWX, pp = gp - b*HWX;
    const int tid = threadIdx.x, ty = tid >> 4, tx = tid & 15;
    U64 acc[4][8], acc2[4][8];
    #pragma unroll
    for (int j = 0; j < 4; j++)
        #pragma unroll
        for (int p = 0; p < 8; p++) { acc[j][p] = 0ULL; acc2[j][p] = 0ULL; }

    for (int kc = 0; kc < 24; kc++) {
        const float* src = kc < 8 ? r1 : (kc < 16 ? r2 : r3);
        int chb = (kc & 7)*16;
        { const float* sp = &src[((b*128 + chb + ty)*HWX) + pp + tx*8];
          *reinterpret_cast<float4*>(&in_s[ty*128 + tx*8])     = *reinterpret_cast<const float4*>(sp);
          *reinterpret_cast<float4*>(&in_s[ty*128 + tx*8 + 4]) = *reinterpret_cast<const float4*>(sp + 4); }
        for (int t2 = tid; t2 < 512; t2 += 256) {
            int oc = t2 >> 2, q = t2 & 3;
            float4 v = *reinterpret_cast<const float4*>(&c5w[oc*384 + kc*16 + q*4]);
            w_s[(q*4+0)*128 + oc] = v.x; w_s[(q*4+1)*128 + oc] = v.y;
            w_s[(q*4+2)*128 + oc] = v.z; w_s[(q*4+3)*128 + oc] = v.w;
        }
        __syncthreads();
        gemm_chunk_f2(in_s, w_s, ty, tx, acc);
        __syncthreads();
    }
    for (int kc = 0; kc < 4; kc++) {
        { const float* sp = &x[((b*64 + kc*16 + ty)*HWX) + pp + tx*8];
          *reinterpret_cast<float4*>(&in_s[ty*128 + tx*8])     = *reinterpret_cast<const float4*>(sp);
          *reinterpret_cast<float4*>(&in_s[ty*128 + tx*8 + 4]) = *reinterpret_cast<const float4*>(sp + 4); }
        for (int t2 = tid; t2 < 512; t2 += 256) {
            int oc = t2 >> 2, q = t2 & 3;
            float4 v = *reinterpret_cast<const float4*>(&c1w[oc*64 + kc*16 + q*4]);
            w_s[(q*4+0)*128 + oc] = v.x; w_s[(q*4+1)*128 + oc] = v.y;
            w_s[(q*4+2)*128 + oc] = v.z; w_s[(q*4+3)*128 + oc] = v.w;
        }
        __syncthreads();
        gemm_chunk_f2(in_s, w_s, ty, tx, acc2);
        __syncthreads();
    }
    #pragma unroll
    for (int j = 0; j < 4; j++) {
        float lo[8], hi[8], lo2[8], hi2[8];
        #pragma unroll
        for (int p = 0; p < 8; p++) {
            unsigned a, c; UNPK2(a, c, acc[j][p]);
            lo[p] = __uint_as_float(a); hi[p] = __uint_as_float(c);
            UNPK2(a, c, acc2[j][p]);
            lo2[p] = __uint_as_float(a); hi2[p] = __uint_as_float(c);
        }
        int oc0 = ty*8 + 2*j;
        #pragma unroll
        for (int hh2 = 0; hh2 < 2; hh2++) {
            int oc = oc0 + hh2;
            const float* m  = hh2 ? hi  : lo;
            const float* m2 = hh2 ? hi2 : lo2;
            float b5 = c5b[oc], b1 = c1b[oc], s = bns[oc], bb2 = bnb[oc];
            float zt[8];
            #pragma unroll
            for (int p = 0; p < 8; p++)
                zt[p] = s*lrelu01(m[p] + b5) + bb2 + lrelu01(m2[p] + b1);
            float* op = &out[((b*128 + oc)*HWX) + pp + tx*8];
            *reinterpret_cast<float4*>(op)     = make_float4(zt[0], zt[1], zt[2], zt[3]);
            *reinterpret_cast<float4*>(op + 4) = make_float4(zt[4], zt[5], zt[6], zt[7]);
        }
    }
}

// =====================================================================
// WeightNet: gxyz -> 8 -> 8 -> 16, per (b, k, pixel)
// =====================================================================
__global__ __launch_bounds__(256)
void weightnet_k(const float* __restrict__ xyz,
                 const float* __restrict__ w1w, const float* __restrict__ w1b,
                 const float* __restrict__ w2w, const float* __restrict__ w2b,
                 const float* __restrict__ w3w, const float* __restrict__ w3b,
                 const float* __restrict__ s1, const float* __restrict__ b1,
                 const float* __restrict__ s2, const float* __restrict__ b2,
                 const float* __restrict__ s3, const float* __restrict__ b3,
                 float* __restrict__ out)
{
    int g = blockIdx.x*256 + threadIdx.x;   // B*25*NP2 = 819200
    int pix = g & (NP2 - 1);
    int rest = g >> 14;
    int k = rest % 25, b = rest / 25;
    int h2 = pix >> 9, w2 = pix & 511;
    int hi = 2*h2 - 2 + k/5, wi = 2*w2 - 2 + (k % 5);
    bool inb = ((unsigned)hi < (unsigned)HH) && ((unsigned)wi < (unsigned)WW);
    float gv[3];
    #pragma unroll
    for (int c = 0; c < 3; c++) {
        float ctr = xyz[(b*3 + c)*HWX + (2*h2)*WW + 2*w2];
        float nb  = inb ? xyz[(b*3 + c)*HWX + hi*WW + wi] : 0.f;
        gv[c] = nb - ctr;
    }
    float a1[8];
    #pragma unroll
    for (int j = 0; j < 8; j++) {
        float z = w1b[j];
        #pragma unroll
        for (int c = 0; c < 3; c++) z += w1w[j*3 + c]*gv[c];
        z = s1[j]*z + b1[j];
        a1[j] = z > 0.f ? z : 0.f;
    }
    float a2[8];
    #pragma unroll
    for (int j = 0; j < 8; j++) {
        float z = w2b[j];
        #pragma unroll
        for (int i = 0; i < 8; i++) z += w2w[j*8 + i]*a1[i];
        z = s2[j]*z + b2[j];
        a2[j] = z > 0.f ? z : 0.f;
    }
    float o[16];
    #pragma unroll
    for (int n = 0; n < 16; n++) {
        float z = w3b[n];
        #pragma unroll
        for (int i = 0; i < 8; i++) z += w3w[n*8 + i]*a2[i];
        z = s3[n]*z + b3[n];
        o[n] = z > 0.f ? z : 0.f;
    }
    size_t base = (((size_t)(b*NP2 + pix))*25 + k)*16;
    #pragma unroll
    for (int q = 0; q < 4; q++)
        *reinterpret_cast<float4*>(&out[base + q*4]) =
            make_float4(o[q*4], o[q*4+1], o[q*4+2], o[q*4+3]);
}

// =====================================================================
// Einsum: y[pix][c*16+n] = sum_k unf(hT)[c][k] * wn[pix][k][n], 2 pixels/block
// =====================================================================
__global__ __launch_bounds__(128)
void einsum_k(const float* __restrict__ hT, const float* __restrict__ wn,
              float* __restrict__ y)
{
    __shared__ float u_s[2][128][25];
    __shared__ float wn_s[2][400];
    const int gpix = blockIdx.x*2;
    const int b = gpix / NP2;
    const int tid = threadIdx.x;

    for (int i = tid; i < 800; i += 128) {
        int pl = i / 400, r = i - pl*400;
        wn_s[pl][r] = wn[(size_t)(gpix + pl)*400 + r];
    }
    for (int idx = 0; idx < 50; idx++) {
        int pl = idx / 25, k = idx - pl*25;
        int pp = (gpix + pl) - b*NP2;
        int h2 = pp >> 9, w2 = pp & 511;
        int hi = 2*h2 - 2 + k/5, wi = 2*w2 - 2 + (k % 5);
        float v = 0.f;
        if ((unsigned)hi < (unsigned)HH && (unsigned)wi < (unsigned)WW)
            v = hT[((size_t)(b*HH + hi)*WW + wi)*128 + tid];
        u_s[pl][tid][k] = v;
    }
    __syncthreads();

    const int s = tid & 63, pl = tid >> 6;
    const int cg = s & 15, ng = s >> 4;
    float acc[8][4];
    #pragma unroll
    for (int i = 0; i < 8; i++)
        #pragma unroll
        for (int n = 0; n < 4; n++) acc[i][n] = 0.f;

    #pragma unroll
    for (int k = 0; k < 25; k++) {
        float u[8];
        #pragma unroll
        for (int i = 0; i < 8; i++) u[i] = u_s[pl][cg*8 + i][k];
        float4 wv = *reinterpret_cast<const float4*>(&wn_s[pl][k*16 + ng*4]);
        float wvv[4] = {wv.x, wv.y, wv.z, wv.w};
        #pragma unroll
        for (int i = 0; i < 8; i++)
            #pragma unroll
            for (int n = 0; n < 4; n++) acc[i][n] += u[i]*wvv[n];
    }
    size_t base = (size_t)(gpix + pl)*2048;
    #pragma unroll
    for (int i = 0; i < 8; i++)
        *reinterpret_cast<float4*>(&y[base + (cg*8 + i)*16 + ng*4]) =
            make_float4(acc[i][0], acc[i][1], acc[i][2], acc[i][3]);
}

// =====================================================================
// Final GEMM: K=2048, y pixel-major in, resB NCHW out, relu(bn(.)), f32x2
// =====================================================================
__global__ __launch_bounds__(256)
void final_f2_k(const float* __restrict__ y, const float* __restrict__ lw,
                const float* __restrict__ lb, const float* __restrict__ bns,
                const float* __restrict__ bnb, float* __restrict__ out)
{
    __shared__ __align__(16) float sraw[4096];
    float* in_s = sraw;
    float* w_s  = sraw + 2048;
    const int gp = blockIdx.x * 128;          // over B*NP2
    const int b = gp / NP2, pp = gp - b*NP2;
    const int tid = threadIdx.x, ty = tid >> 4, tx = tid & 15;
    U64 acc[4][8];
    #pragma unroll
    for (int j = 0; j < 4; j++)
        #pragma unroll
        for (int p = 0; p < 8; p++) acc[j][p] = 0ULL;

    for (int kc = 0; kc < 128; kc++) {
        for (int t2 = tid; t2 < 512; t2 += 256) {
            int pix = t2 >> 2, q = t2 & 3;
            float4 v = *reinterpret_cast<const float4*>(&y[(size_t)(gp + pix)*2048 + kc*16 + q*4]);
            in_s[(q*4+0)*128 + pix] = v.x; in_s[(q*4+1)*128 + pix] = v.y;
            in_s[(q*4+2)*128 + pix] = v.z; in_s[(q*4+3)*128 + pix] = v.w;
        }
        for (int t2 = tid; t2 < 512; t2 += 256) {
            int oc = t2 >> 2, q = t2 & 3;
            float4 v = *reinterpret_cast<const float4*>(&lw[oc*2048 + kc*16 + q*4]);
            w_s[(q*4+0)*128 + oc] = v.x; w_s[(q*4+1)*128 + oc] = v.y;
            w_s[(q*4+2)*128 + oc] = v.z; w_s[(q*4+3)*128 + oc] = v.w;
        }
        __syncthreads();
        gemm_chunk_f2(in_s, w_s, ty, tx, acc);
        __syncthreads();
    }
    #pragma unroll
    for (int j = 0; j < 4; j++) {
        float lo[8], hi[8];
        #pragma unroll
        for (int p = 0; p < 8; p++) {
            unsigned a, c; UNPK2(a, c, acc[j][p]);
            lo[p] = __uint_as_float(a); hi[p] = __uint_as_float(c);
        }
        int oc0 = ty*8 + 2*j;
        #pragma unroll
        for (int hh2 = 0; hh2 < 2; hh2++) {
            int oc = oc0 + hh2;
            const float* src = hh2 ? hi : lo;
            float bi = lb[oc], s = bns[oc], bb2 = bnb[oc];
            float zt[8];
            #pragma unroll
            for (int p = 0; p < 8; p++) {
                float z = s*(src[p] + bi) + bb2;
                zt[p] = z > 0.f ? z : 0.f;
            }
            float* op = &out[((b*128 + oc)*NP2) + pp + tx*8];
            *reinterpret_cast<float4*>(op)     = make_float4(zt[0], zt[1], zt[2], zt[3]);
            *reinterpret_cast<float4*>(op + 4) = make_float4(zt[4], zt[5], zt[6], zt[7]);
        }
    }
}

// =====================================================================
// host launcher
// =====================================================================
extern "C" void kernel_launch(void* const* d_in, const int* in_sizes, int n_in,
                              void* d_out, int out_size)
{
    const float* x      = (const float*)d_in[0];
    const float* xyz    = (const float*)d_in[1];
    const float* c1_w   = (const float*)d_in[2];
    const float* c1_b   = (const float*)d_in[3];
    const float* c2_w   = (const float*)d_in[4];
    const float* c2_b   = (const float*)d_in[5];
    const float* c3_w   = (const float*)d_in[6];
    const float* c3_b   = (const float*)d_in[7];
    const float* c4_w   = (const float*)d_in[8];
    const float* c4_b   = (const float*)d_in[9];
    const float* c5_w   = (const float*)d_in[10];
    const float* c5_b   = (const float*)d_in[11];
    const float* rbn_s  = (const float*)d_in[12];
    const float* rbn_b  = (const float*)d_in[13];
    const float* p_w    = (const float*)d_in[14];
    const float* p_b    = (const float*)d_in[15];
    const float* pbn_s  = (const float*)d_in[16];
    const float* pbn_b  = (const float*)d_in[17];
    const float* lin_w  = (const float*)d_in[18];
    const float* lin_b  = (const float*)d_in[19];
    const float* w1_w   = (const float*)d_in[20];
    const float* w1_b   = (const float*)d_in[21];
    const float* w2_w   = (const float*)d_in[22];
    const float* w2_b   = (const float*)d_in[23];
    const float* w3_w   = (const float*)d_in[24];
    const float* w3_b   = (const float*)d_in[25];
    const float* wbn1_s = (const float*)d_in[26];
    const float* wbn1_b = (const float*)d_in[27];
    const float* wbn2_s = (const float*)d_in[28];
    const float* wbn2_b = (const float*)d_in[29];
    const float* wbn3_s = (const float*)d_in[30];
    const float* wbn3_b = (const float*)d_in[31];

    float* outp = (float*)d_out;
    float* resB = outp;                 // [B,128,H2,W2]
    float* resA = outp + RESB_ELEMS;    // [B,128,H,W]

    float *A1, *A2, *A3, *B1, *B2, *HT, *WN, *Y;
    cudaGetSymbolAddress((void**)&A1, g_resA1);
    cudaGetSymbolAddress((void**)&A2, g_resA2);
    cudaGetSymbolAddress((void**)&A3, g_resA3);
    cudaGetSymbolAddress((void**)&B1, g_buf1);
    cudaGetSymbolAddress((void**)&B2, g_buf2);
    cudaGetSymbolAddress((void**)&HT, g_hT);
    cudaGetSymbolAddress((void**)&WN, g_wn);
    cudaGetSymbolAddress((void**)&Y,  g_y);

    dim3 cgrid(WW/128, HH, BB);
    // ResBlock trunk
    conv_f2_k<64, 3, 1, 1><<<cgrid, 256>>>(x,  c2_w, c2_b, rbn_s,       rbn_b,       A1);
    conv_f2_k<128,3, 2, 2><<<cgrid, 256>>>(A1, c3_w, c3_b, rbn_s + 128, rbn_b + 128, A2);
    conv_f2_k<128,2, 2, 1><<<cgrid, 256>>>(A2, c4_w, c4_b, rbn_s + 256, rbn_b + 256, A3);
    resa_f2_k<<<BB*HWX/128, 256>>>(A1, A2, A3, x, c5_w, c5_b, c1_w, c1_b,
                                   rbn_s + 384, rbn_b + 384, resA);
    // Pointwise MLP (3rd layer writes transposed for the unfold gather)
    gemm128_f2_k<0><<<BB*HWX/128, 256>>>(resA, p_w,          p_b,       pbn_s,       pbn_b,       B1);
    gemm128_f2_k<0><<<BB*HWX/128, 256>>>(B1,   p_w + 16384,  p_b + 128, pbn_s + 128, pbn_b + 128, B2);
    gemm128_f2_k<1><<<BB*HWX/128, 256>>>(B2,   p_w + 32768,  p_b + 256, pbn_s + 256, pbn_b + 256, HT);
    // WeightNet on geometry
    weightnet_k<<<(BB*25*NP2)/256, 256>>>(xyz, w1_w, w1_b, w2_w, w2_b, w3_w, w3_b,
                                          wbn1_s, wbn1_b, wbn2_s, wbn2_b, wbn3_s, wbn3_b, WN);
    // unfold x wn einsum -> y (pixel-major)
    einsum_k<<<BB*NP2/2, 128>>>(HT, WN, Y);
    // final 128x2048 pointwise GEMM -> resB
    final_f2_k<<<BB*NP2/128, 256>>>(Y, lin_w, lin_b, pbn_s + 384, pbn_b + 384, resB);
}

// round 6
// speedup vs baseline: 1.5437x; 1.3419x over previous
#include <cuda_runtime.h>
#include <cstddef>

// ---------------- problem constants ----------------
#define BB   2
#define CINX 64
#define CH   128
#define HH   64
#define WW   1024
#define HWX  (HH*WW)          // 65536
#define H2X  32
#define W2X  512
#define NP2  (H2X*W2X)        // 16384
#define RESB_ELEMS (BB*CH*NP2)   // 4194304

typedef unsigned long long U64;

// f32x2 packed FMA (Blackwell): c = a*b + c elementwise on 2 packed fp32
#define FMA2(c, a, b) asm("fma.rn.f32x2 %0, %1, %2, %0;" : "+l"(c) : "l"(a), "l"(b))
#define PACK2(d, x)   asm("mov.b64 %0, {%1, %1};" : "=l"(d) : "r"(__float_as_uint(x)))
#define UNPK2(lo, hi, d) asm("mov.b64 {%0, %1}, %2;" : "=r"(lo), "=r"(hi) : "l"(d))

// ---------------- scratch (static device memory; no allocation) ----------------
__device__ float g_resA1[BB*CH*HWX];
__device__ float g_resA2[BB*CH*HWX];
__device__ float g_resA3[BB*CH*HWX];
__device__ float g_buf1 [BB*CH*HWX];
__device__ float g_buf2 [BB*CH*HWX];
__device__ float g_hT   [BB*HWX*CH];          // transposed h: [B][H][W][C]
__device__ float g_wn   [BB*NP2*25*16];       // [B*NP2][25][16]
__device__ float g_y    [(size_t)BB*NP2*2048];// pixel-major: [B*NP2][2048]

__device__ __forceinline__ float lrelu01(float z) { return z > 0.f ? z : 0.01f*z; }

// =====================================================================
// Shared GEMM inner: 16-K chunk, 4 oc-pair x 8 px per thread, f32x2
// in_s: [16][128] pixel-minor; w_s: [16][128] oc-minor
// =====================================================================
__device__ __forceinline__ void gemm_chunk_f2(const float* __restrict__ in_s,
                                              const float* __restrict__ w_s,
                                              int ty, int tx, U64 acc[4][8])
{
    #pragma unroll
    for (int kk = 0; kk < 16; kk++) {
        ulonglong2 wa = *reinterpret_cast<const ulonglong2*>(w_s + kk*128 + ty*8);
        ulonglong2 wb = *reinterpret_cast<const ulonglong2*>(w_s + kk*128 + ty*8 + 4);
        U64 wp[4] = {wa.x, wa.y, wb.x, wb.y};
        float4 xa = *reinterpret_cast<const float4*>(in_s + kk*128 + tx*8);
        float4 xb = *reinterpret_cast<const float4*>(in_s + kk*128 + tx*8 + 4);
        float xs[8] = {xa.x, xa.y, xa.z, xa.w, xb.x, xb.y, xb.z, xb.w};
        U64 xp[8];
        #pragma unroll
        for (int p = 0; p < 8; p++) PACK2(xp[p], xs[p]);
        #pragma unroll
        for (int j = 0; j < 4; j++)
            #pragma unroll
            for (int p = 0; p < 8; p++)
                FMA2(acc[j][p], wp[j], xp[p]);
    }
}

// =====================================================================
// Direct conv, pipelined: block = 64 oc x 256 px (one row), CC=4 input chans/chunk
// bn(lrelu(conv+b)), f32x2, register double-buffer, 2 barriers/chunk
// =====================================================================
template<int CIN, int KS, int DIL, int PAD>
__global__ __launch_bounds__(256)
void conv_f2_k(const float* __restrict__ in, const float* __restrict__ wg,
               const float* __restrict__ bias, const float* __restrict__ bns,
               const float* __restrict__ bnb, float* __restrict__ out)
{
    constexpr int CC = 4, WT = 256, KK = KS*KS, IWP = 260;
    constexpr int INTOT = CC*KS*IWP;                 // smem input floats
    constexpr int NIN   = (INTOT + 255)/256;         // per-thread input prefetch
    constexpr int WTOT  = CC*KK*64;                  // smem weight floats
    constexpr int NW    = (WTOT + 1023)/1024;        // per-thread w float4 prefetch
    constexpr int WPO   = CC*KK;                     // weights per oc per chunk
    constexpr int NCH   = CIN/CC;

    __shared__ __align__(16) float in_s[INTOT];
    __shared__ __align__(16) float w_s[WTOT];

    const int bx  = blockIdx.x;
    const int w0  = (bx >> 1) * WT;
    const int oc0 = (bx & 1) * 64;
    const int h   = blockIdx.y;
    const int b   = blockIdx.z;
    const int tid = threadIdx.x;
    const int ty = tid >> 5, tx = tid & 31;

    U64 acc[4][8];
    #pragma unroll
    for (int j = 0; j < 4; j++)
        #pragma unroll
        for (int p = 0; p < 8; p++) acc[j][p] = 0ULL;

    float  rin[NIN];
    float4 rw[NW];

    // ---- prefetch helpers (inline) ----
    auto load_chunk = [&](int cb, float rin_[NIN], float4 rw_[NW]) {
        #pragma unroll
        for (int j = 0; j < NIN; j++) {
            int idx = tid + j*256;
            float v = 0.f;
            if (idx < INTOT) {
                int ci  = idx / (KS*IWP);
                int rem = idx - ci*(KS*IWP);
                int r = rem / IWP, col = rem - r*IWP;
                int gy = h - PAD + r*DIL;
                int gx = w0 - PAD + col;
                if ((unsigned)gy < (unsigned)HH && (unsigned)gx < (unsigned)WW)
                    v = in[((b*CIN + cb + ci)*HH + gy)*WW + gx];
            }
            rin_[j] = v;
        }
        #pragma unroll
        for (int j = 0; j < NW; j++) {
            int idx = tid*4 + j*1024;
            if (idx < WTOT) {
                int ocl = idx / WPO;
                int r   = idx - ocl*WPO;
                rw_[j] = *reinterpret_cast<const float4*>(&wg[((oc0 + ocl)*CIN + cb)*KK + r]);
            }
        }
    };

    load_chunk(0, rin, rw);

    for (int c = 0; c < NCH; c++) {
        __syncthreads();
        // store prefetched regs -> smem
        #pragma unroll
        for (int j = 0; j < NIN; j++) {
            int idx = tid + j*256;
            if (idx < INTOT) in_s[idx] = rin[j];
        }
        #pragma unroll
        for (int j = 0; j < NW; j++) {
            int idx = tid*4 + j*1024;
            if (idx < WTOT) {
                int ocl = idx / WPO;
                int r   = idx - ocl*WPO;
                float vv[4] = {rw[j].x, rw[j].y, rw[j].z, rw[j].w};
                #pragma unroll
                for (int jj = 0; jj < 4; jj++)
                    w_s[(r + jj)*64 + ocl] = vv[jj];
            }
        }
        __syncthreads();
        if (c + 1 < NCH) load_chunk((c + 1)*CC, rin, rw);

        // compute
        #pragma unroll
        for (int ci = 0; ci < CC; ci++) {
            #pragma unroll
            for (int kh = 0; kh < KS; kh++) {
                const float* xrow = in_s + (ci*KS + kh)*IWP + tx*8;
                float xr[12];
                *reinterpret_cast<float4*>(&xr[0]) = *reinterpret_cast<const float4*>(xrow);
                *reinterpret_cast<float4*>(&xr[4]) = *reinterpret_cast<const float4*>(xrow + 4);
                *reinterpret_cast<float4*>(&xr[8]) = *reinterpret_cast<const float4*>(xrow + 8);
                #pragma unroll
                for (int kw = 0; kw < KS; kw++) {
                    const float* wrow = w_s + (ci*KK + kh*KS + kw)*64 + ty*8;
                    ulonglong2 wa = *reinterpret_cast<const ulonglong2*>(wrow);
                    ulonglong2 wb = *reinterpret_cast<const ulonglong2*>(wrow + 4);
                    U64 wp[4] = {wa.x, wa.y, wb.x, wb.y};
                    U64 xp[8];
                    #pragma unroll
                    for (int p = 0; p < 8; p++) PACK2(xp[p], xr[p + kw*DIL]);
                    #pragma unroll
                    for (int j = 0; j < 4; j++)
                        #pragma unroll
                        for (int p = 0; p < 8; p++)
                            FMA2(acc[j][p], wp[j], xp[p]);
                }
            }
        }
    }
    #pragma unroll
    for (int j = 0; j < 4; j++) {
        float lo[8], hi[8];
        #pragma unroll
        for (int p = 0; p < 8; p++) {
            unsigned a, c; UNPK2(a, c, acc[j][p]);
            lo[p] = __uint_as_float(a); hi[p] = __uint_as_float(c);
        }
        #pragma unroll
        for (int hh2 = 0; hh2 < 2; hh2++) {
            int oc = oc0 + ty*8 + 2*j + hh2;
            const float* src = hh2 ? hi : lo;
            float bi = bias[oc], s = bns[oc], bb2 = bnb[oc];
            float zt[8];
            #pragma unroll
            for (int p = 0; p < 8; p++) zt[p] = s*lrelu01(src[p] + bi) + bb2;
            float* op = &out[((b*128 + oc)*HH + h)*WW + w0 + tx*8];
            *reinterpret_cast<float4*>(op)     = make_float4(zt[0], zt[1], zt[2], zt[3]);
            *reinterpret_cast<float4*>(op + 4) = make_float4(zt[4], zt[5], zt[6], zt[7]);
        }
    }
}

// =====================================================================
// Pointwise 128->128, pipelined, NCHW in, relu(bn(Wx+b)).
// TR=1 writes transposed [pix][C]. 128 px per block.
// =====================================================================
template<int TR>
__global__ __launch_bounds__(256)
void gemm128_f2_k(const float* __restrict__ in, const float* __restrict__ wg,
                  const float* __restrict__ bias, const float* __restrict__ bns,
                  const float* __restrict__ bnb, float* __restrict__ out)
{
    __shared__ __align__(16) float sraw[4224];
    float* in_s = sraw;          // [16][128]
    float* w_s  = sraw + 2048;   // [16][128]
    const int gp = blockIdx.x * 128;
    const int b = gp / HWX, pp = gp - b*HWX;
    const int tid = threadIdx.x, ty = tid >> 4, tx = tid & 15;
    const int oc1 = tid >> 2, q1 = tid & 3;
    U64 acc[4][8];
    #pragma unroll
    for (int j = 0; j < 4; j++)
        #pragma unroll
        for (int p = 0; p < 8; p++) acc[j][p] = 0ULL;

    float4 ra, rb, rwa, rwb;
    auto load_chunk = [&](int kc) {
        const float* sp = &in[((b*128 + kc*16 + ty)*HWX) + pp + tx*8];
        ra = *reinterpret_cast<const float4*>(sp);
        rb = *reinterpret_cast<const float4*>(sp + 4);
        rwa = *reinterpret_cast<const float4*>(&wg[oc1*128 + kc*16 + q1*4]);
        rwb = *reinterpret_cast<const float4*>(&wg[(oc1 + 64)*128 + kc*16 + q1*4]);
    };

    load_chunk(0);
    for (int kc = 0; kc < 8; kc++) {
        __syncthreads();
        *reinterpret_cast<float4*>(&in_s[ty*128 + tx*8])     = ra;
        *reinterpret_cast<float4*>(&in_s[ty*128 + tx*8 + 4]) = rb;
        w_s[(q1*4+0)*128 + oc1] = rwa.x; w_s[(q1*4+1)*128 + oc1] = rwa.y;
        w_s[(q1*4+2)*128 + oc1] = rwa.z; w_s[(q1*4+3)*128 + oc1] = rwa.w;
        w_s[(q1*4+0)*128 + oc1+64] = rwb.x; w_s[(q1*4+1)*128 + oc1+64] = rwb.y;
        w_s[(q1*4+2)*128 + oc1+64] = rwb.z; w_s[(q1*4+3)*128 + oc1+64] = rwb.w;
        __syncthreads();
        if (kc + 1 < 8) load_chunk(kc + 1);
        gemm_chunk_f2(in_s, w_s, ty, tx, acc);
    }

    if (TR == 0) {
        #pragma unroll
        for (int j = 0; j < 4; j++) {
            float lo[8], hi[8];
            #pragma unroll
            for (int p = 0; p < 8; p++) {
                unsigned a, c; UNPK2(a, c, acc[j][p]);
                lo[p] = __uint_as_float(a); hi[p] = __uint_as_float(c);
            }
            #pragma unroll
            for (int hh2 = 0; hh2 < 2; hh2++) {
                int oc = ty*8 + 2*j + hh2;
                const float* src = hh2 ? hi : lo;
                float bi = bias[oc], s = bns[oc], bb2 = bnb[oc];
                float zt[8];
                #pragma unroll
                for (int p = 0; p < 8; p++) {
                    float z = s*(src[p] + bi) + bb2;
                    zt[p] = z > 0.f ? z : 0.f;
                }
                float* op = &out[((b*128 + oc)*HWX) + pp + tx*8];
                *reinterpret_cast<float4*>(op)     = make_float4(zt[0], zt[1], zt[2], zt[3]);
                *reinterpret_cast<float4*>(op + 4) = make_float4(zt[4], zt[5], zt[6], zt[7]);
            }
        }
    } else {
        // 4-pass transpose via smem staging (reuses sraw)
        float* stage = sraw;   // [32][129]
        for (int g = 0; g < 4; g++) {
            __syncthreads();
            if ((ty >> 2) == g) {
                #pragma unroll
                for (int j = 0; j < 4; j++) {
                    unsigned a, c;
                    float lo[8], hi[8];
                    #pragma unroll
                    for (int p = 0; p < 8; p++) {
                        UNPK2(a, c, acc[j][p]);
                        lo[p] = __uint_as_float(a); hi[p] = __uint_as_float(c);
                    }
                    int oc = ty*8 + 2*j;
                    int ocl = oc - g*32;
                    float bi0 = bias[oc],   s0 = bns[oc],   b0 = bnb[oc];
                    float bi1 = bias[oc+1], s1 = bns[oc+1], b1 = bnb[oc+1];
                    #pragma unroll
                    for (int p = 0; p < 8; p++) {
                        float z0 = s0*(lo[p] + bi0) + b0;
                        float z1 = s1*(hi[p] + bi1) + b1;
                        stage[ocl*129 + tx*8 + p]     = z0 > 0.f ? z0 : 0.f;
                        stage[(ocl+1)*129 + tx*8 + p] = z1 > 0.f ? z1 : 0.f;
                    }
                }
            }
            __syncthreads();
            for (int t2 = tid; t2 < 1024; t2 += 256) {
                int pix = t2 >> 3, c4 = t2 & 7;
                float4 v;
                v.x = stage[(c4*4+0)*129 + pix];
                v.y = stage[(c4*4+1)*129 + pix];
                v.z = stage[(c4*4+2)*129 + pix];
                v.w = stage[(c4*4+3)*129 + pix];
                *reinterpret_cast<float4*>(&out[(size_t)(b*HWX + pp + pix)*128 + g*32 + c4*4]) = v;
            }
        }
    }
}

// =====================================================================
// resA: bn3(lrelu(c5 @ concat + c5_b)) + lrelu(c1 @ x + c1_b), pipelined f32x2
// =====================================================================
__global__ __launch_bounds__(256)
void resa_f2_k(const float* __restrict__ r1, const float* __restrict__ r2,
               const float* __restrict__ r3, const float* __restrict__ x,
               const float* __restrict__ c5w, const float* __restrict__ c5b,
               const float* __restrict__ c1w, const float* __restrict__ c1b,
               const float* __restrict__ bns, const float* __restrict__ bnb,
               float* __restrict__ out)
{
    __shared__ __align__(16) float sraw[4096];
    float* in_s = sraw;
    float* w_s  = sraw + 2048;
    const int gp = blockIdx.x * 128;
    const int b = gp / HWX, pp = gp - b*HWX;
    const int tid = threadIdx.x, ty = tid >> 4, tx = tid & 15;
    const int oc1 = tid >> 2, q1 = tid & 3;
    U64 acc[4][8], acc2[4][8];
    #pragma unroll
    for (int j = 0; j < 4; j++)
        #pragma unroll
        for (int p = 0; p < 8; p++) { acc[j][p] = 0ULL; acc2[j][p] = 0ULL; }

    float4 ra, rb, rwa, rwb;
    auto load_p1 = [&](int kc) {
        const float* src = kc < 8 ? r1 : (kc < 16 ? r2 : r3);
        int chb = (kc & 7)*16;
        const float* sp = &src[((b*128 + chb + ty)*HWX) + pp + tx*8];
        ra = *reinterpret_cast<const float4*>(sp);
        rb = *reinterpret_cast<const float4*>(sp + 4);
        rwa = *reinterpret_cast<const float4*>(&c5w[oc1*384 + kc*16 + q1*4]);
        rwb = *reinterpret_cast<const float4*>(&c5w[(oc1 + 64)*384 + kc*16 + q1*4]);
    };
    auto load_p2 = [&](int kc) {
        const float* sp = &x[((b*64 + kc*16 + ty)*HWX) + pp + tx*8];
        ra = *reinterpret_cast<const float4*>(sp);
        rb = *reinterpret_cast<const float4*>(sp + 4);
        rwa = *reinterpret_cast<const float4*>(&c1w[oc1*64 + kc*16 + q1*4]);
        rwb = *reinterpret_cast<const float4*>(&c1w[(oc1 + 64)*64 + kc*16 + q1*4]);
    };
    auto stage_store = [&]() {
        *reinterpret_cast<float4*>(&in_s[ty*128 + tx*8])     = ra;
        *reinterpret_cast<float4*>(&in_s[ty*128 + tx*8 + 4]) = rb;
        w_s[(q1*4+0)*128 + oc1] = rwa.x; w_s[(q1*4+1)*128 + oc1] = rwa.y;
        w_s[(q1*4+2)*128 + oc1] = rwa.z; w_s[(q1*4+3)*128 + oc1] = rwa.w;
        w_s[(q1*4+0)*128 + oc1+64] = rwb.x; w_s[(q1*4+1)*128 + oc1+64] = rwb.y;
        w_s[(q1*4+2)*128 + oc1+64] = rwb.z; w_s[(q1*4+3)*128 + oc1+64] = rwb.w;
    };

    load_p1(0);
    for (int kc = 0; kc < 24; kc++) {
        __syncthreads();
        stage_store();
        __syncthreads();
        if (kc + 1 < 24) load_p1(kc + 1); else load_p2(0);
        gemm_chunk_f2(in_s, w_s, ty, tx, acc);
    }
    for (int kc = 0; kc < 4; kc++) {
        __syncthreads();
        stage_store();
        __syncthreads();
        if (kc + 1 < 4) load_p2(kc + 1);
        gemm_chunk_f2(in_s, w_s, ty, tx, acc2);
    }

    #pragma unroll
    for (int j = 0; j < 4; j++) {
        float lo[8], hi[8], lo2[8], hi2[8];
        #pragma unroll
        for (int p = 0; p < 8; p++) {
            unsigned a, c; UNPK2(a, c, acc[j][p]);
            lo[p] = __uint_as_float(a); hi[p] = __uint_as_float(c);
            UNPK2(a, c, acc2[j][p]);
            lo2[p] = __uint_as_float(a); hi2[p] = __uint_as_float(c);
        }
        #pragma unroll
        for (int hh2 = 0; hh2 < 2; hh2++) {
            int oc = ty*8 + 2*j + hh2;
            const float* m  = hh2 ? hi  : lo;
            const float* m2 = hh2 ? hi2 : lo2;
            float b5 = c5b[oc], b1 = c1b[oc], s = bns[oc], bb2 = bnb[oc];
            float zt[8];
            #pragma unroll
            for (int p = 0; p < 8; p++)
                zt[p] = s*lrelu01(m[p] + b5) + bb2 + lrelu01(m2[p] + b1);
            float* op = &out[((b*128 + oc)*HWX) + pp + tx*8];
            *reinterpret_cast<float4*>(op)     = make_float4(zt[0], zt[1], zt[2], zt[3]);
            *reinterpret_cast<float4*>(op + 4) = make_float4(zt[4], zt[5], zt[6], zt[7]);
        }
    }
}

// =====================================================================
// WeightNet: gxyz -> 8 -> 8 -> 16, per (b, k, pixel)
// =====================================================================
__global__ __launch_bounds__(256)
void weightnet_k(const float* __restrict__ xyz,
                 const float* __restrict__ w1w, const float* __restrict__ w1b,
                 const float* __restrict__ w2w, const float* __restrict__ w2b,
                 const float* __restrict__ w3w, const float* __restrict__ w3b,
                 const float* __restrict__ s1, const float* __restrict__ b1,
                 const float* __restrict__ s2, const float* __restrict__ b2,
                 const float* __restrict__ s3, const float* __restrict__ b3,
                 float* __restrict__ out)
{
    int g = blockIdx.x*256 + threadIdx.x;   // B*25*NP2 = 819200
    int pix = g & (NP2 - 1);
    int rest = g >> 14;
    int k = rest % 25, b = rest / 25;
    int h2 = pix >> 9, w2 = pix & 511;
    int hi = 2*h2 - 2 + k/5, wi = 2*w2 - 2 + (k % 5);
    bool inb = ((unsigned)hi < (unsigned)HH) && ((unsigned)wi < (unsigned)WW);
    float gv[3];
    #pragma unroll
    for (int c = 0; c < 3; c++) {
        float ctr = xyz[(b*3 + c)*HWX + (2*h2)*WW + 2*w2];
        float nb  = inb ? xyz[(b*3 + c)*HWX + hi*WW + wi] : 0.f;
        gv[c] = nb - ctr;
    }
    float a1[8];
    #pragma unroll
    for (int j = 0; j < 8; j++) {
        float z = w1b[j];
        #pragma unroll
        for (int c = 0; c < 3; c++) z += w1w[j*3 + c]*gv[c];
        z = s1[j]*z + b1[j];
        a1[j] = z > 0.f ? z : 0.f;
    }
    float a2[8];
    #pragma unroll
    for (int j = 0; j < 8; j++) {
        float z = w2b[j];
        #pragma unroll
        for (int i = 0; i < 8; i++) z += w2w[j*8 + i]*a1[i];
        z = s2[j]*z + b2[j];
        a2[j] = z > 0.f ? z : 0.f;
    }
    float o[16];
    #pragma unroll
    for (int n = 0; n < 16; n++) {
        float z = w3b[n];
        #pragma unroll
        for (int i = 0; i < 8; i++) z += w3w[n*8 + i]*a2[i];
        z = s3[n]*z + b3[n];
        o[n] = z > 0.f ? z : 0.f;
    }
    size_t base = (((size_t)(b*NP2 + pix))*25 + k)*16;
    #pragma unroll
    for (int q = 0; q < 4; q++)
        *reinterpret_cast<float4*>(&out[base + q*4]) =
            make_float4(o[q*4], o[q*4+1], o[q*4+2], o[q*4+3]);
}

// =====================================================================
// Einsum: y[pix][c*16+n] = sum_k unf(hT)[c][k] * wn[pix][k][n], 2 pixels/block
// =====================================================================
__global__ __launch_bounds__(128)
void einsum_k(const float* __restrict__ hT, const float* __restrict__ wn,
              float* __restrict__ y)
{
    __shared__ float u_s[2][128][25];
    __shared__ float wn_s[2][400];
    const int gpix = blockIdx.x*2;
    const int b = gpix / NP2;
    const int tid = threadIdx.x;

    for (int i = tid; i < 800; i += 128) {
        int pl = i / 400, r = i - pl*400;
        wn_s[pl][r] = wn[(size_t)(gpix + pl)*400 + r];
    }
    for (int idx = 0; idx < 50; idx++) {
        int pl = idx / 25, k = idx - pl*25;
        int pp = (gpix + pl) - b*NP2;
        int h2 = pp >> 9, w2 = pp & 511;
        int hi = 2*h2 - 2 + k/5, wi = 2*w2 - 2 + (k % 5);
        float v = 0.f;
        if ((unsigned)hi < (unsigned)HH && (unsigned)wi < (unsigned)WW)
            v = hT[((size_t)(b*HH + hi)*WW + wi)*128 + tid];
        u_s[pl][tid][k] = v;
    }
    __syncthreads();

    const int s = tid & 63, pl = tid >> 6;
    const int cg = s & 15, ng = s >> 4;
    float acc[8][4];
    #pragma unroll
    for (int i = 0; i < 8; i++)
        #pragma unroll
        for (int n = 0; n < 4; n++) acc[i][n] = 0.f;

    #pragma unroll
    for (int k = 0; k < 25; k++) {
        float u[8];
        #pragma unroll
        for (int i = 0; i < 8; i++) u[i] = u_s[pl][cg*8 + i][k];
        float4 wv = *reinterpret_cast<const float4*>(&wn_s[pl][k*16 + ng*4]);
        float wvv[4] = {wv.x, wv.y, wv.z, wv.w};
        #pragma unroll
        for (int i = 0; i < 8; i++)
            #pragma unroll
            for (int n = 0; n < 4; n++) acc[i][n] += u[i]*wvv[n];
    }
    size_t base = (size_t)(gpix + pl)*2048;
    #pragma unroll
    for (int i = 0; i < 8; i++)
        *reinterpret_cast<float4*>(&y[base + (cg*8 + i)*16 + ng*4]) =
            make_float4(acc[i][0], acc[i][1], acc[i][2], acc[i][3]);
}

// =====================================================================
// Final GEMM: K=2048, y pixel-major in, resB NCHW out, relu(bn(.)), pipelined f32x2
// =====================================================================
__global__ __launch_bounds__(256)
void final_f2_k(const float* __restrict__ y, const float* __restrict__ lw,
                const float* __restrict__ lb, const float* __restrict__ bns,
                const float* __restrict__ bnb, float* __restrict__ out)
{
    __shared__ __align__(16) float sraw[4096];
    float* in_s = sraw;
    float* w_s  = sraw + 2048;
    const int gp = blockIdx.x * 128;          // over B*NP2
    const int b = gp / NP2, pp = gp - b*NP2;
    const int tid = threadIdx.x, ty = tid >> 4, tx = tid & 15;
    const int oc1 = tid >> 2, q1 = tid & 3;   // also pix1/q for in staging
    U64 acc[4][8];
    #pragma unroll
    for (int j = 0; j < 4; j++)
        #pragma unroll
        for (int p = 0; p < 8; p++) acc[j][p] = 0ULL;

    float4 ra, rb, rwa, rwb;
    auto load_chunk = [&](int kc) {
        ra  = *reinterpret_cast<const float4*>(&y[(size_t)(gp + oc1)*2048 + kc*16 + q1*4]);
        rb  = *reinterpret_cast<const float4*>(&y[(size_t)(gp + oc1 + 64)*2048 + kc*16 + q1*4]);
        rwa = *reinterpret_cast<const float4*>(&lw[oc1*2048 + kc*16 + q1*4]);
        rwb = *reinterpret_cast<const float4*>(&lw[(oc1 + 64)*2048 + kc*16 + q1*4]);
    };

    load_chunk(0);
    for (int kc = 0; kc < 128; kc++) {
        __syncthreads();
        in_s[(q1*4+0)*128 + oc1] = ra.x; in_s[(q1*4+1)*128 + oc1] = ra.y;
        in_s[(q1*4+2)*128 + oc1] = ra.z; in_s[(q1*4+3)*128 + oc1] = ra.w;
        in_s[(q1*4+0)*128 + oc1+64] = rb.x; in_s[(q1*4+1)*128 + oc1+64] = rb.y;
        in_s[(q1*4+2)*128 + oc1+64] = rb.z; in_s[(q1*4+3)*128 + oc1+64] = rb.w;
        w_s[(q1*4+0)*128 + oc1] = rwa.x; w_s[(q1*4+1)*128 + oc1] = rwa.y;
        w_s[(q1*4+2)*128 + oc1] = rwa.z; w_s[(q1*4+3)*128 + oc1] = rwa.w;
        w_s[(q1*4+0)*128 + oc1+64] = rwb.x; w_s[(q1*4+1)*128 + oc1+64] = rwb.y;
        w_s[(q1*4+2)*128 + oc1+64] = rwb.z; w_s[(q1*4+3)*128 + oc1+64] = rwb.w;
        __syncthreads();
        if (kc + 1 < 128) load_chunk(kc + 1);
        gemm_chunk_f2(in_s, w_s, ty, tx, acc);
    }
    #pragma unroll
    for (int j = 0; j < 4; j++) {
        float lo[8], hi[8];
        #pragma unroll
        for (int p = 0; p < 8; p++) {
            unsigned a, c; UNPK2(a, c, acc[j][p]);
            lo[p] = __uint_as_float(a); hi[p] = __uint_as_float(c);
        }
        #pragma unroll
        for (int hh2 = 0; hh2 < 2; hh2++) {
            int oc = ty*8 + 2*j + hh2;
            const float* src = hh2 ? hi : lo;
            float bi = lb[oc], s = bns[oc], bb2 = bnb[oc];
            float zt[8];
            #pragma unroll
            for (int p = 0; p < 8; p++) {
                float z = s*(src[p] + bi) + bb2;
                zt[p] = z > 0.f ? z : 0.f;
            }
            float* op = &out[((b*128 + oc)*NP2) + pp + tx*8];
            *reinterpret_cast<float4*>(op)     = make_float4(zt[0], zt[1], zt[2], zt[3]);
            *reinterpret_cast<float4*>(op + 4) = make_float4(zt[4], zt[5], zt[6], zt[7]);
        }
    }
}

// =====================================================================
// host launcher
// =====================================================================
extern "C" void kernel_launch(void* const* d_in, const int* in_sizes, int n_in,
                              void* d_out, int out_size)
{
    const float* x      = (const float*)d_in[0];
    const float* xyz    = (const float*)d_in[1];
    const float* c1_w   = (const float*)d_in[2];
    const float* c1_b   = (const float*)d_in[3];
    const float* c2_w   = (const float*)d_in[4];
    const float* c2_b   = (const float*)d_in[5];
    const float* c3_w   = (const float*)d_in[6];
    const float* c3_b   = (const float*)d_in[7];
    const float* c4_w   = (const float*)d_in[8];
    const float* c4_b   = (const float*)d_in[9];
    const float* c5_w   = (const float*)d_in[10];
    const float* c5_b   = (const float*)d_in[11];
    const float* rbn_s  = (const float*)d_in[12];
    const float* rbn_b  = (const float*)d_in[13];
    const float* p_w    = (const float*)d_in[14];
    const float* p_b    = (const float*)d_in[15];
    const float* pbn_s  = (const float*)d_in[16];
    const float* pbn_b  = (const float*)d_in[17];
    const float* lin_w  = (const float*)d_in[18];
    const float* lin_b  = (const float*)d_in[19];
    const float* w1_w   = (const float*)d_in[20];
    const float* w1_b   = (const float*)d_in[21];
    const float* w2_w   = (const float*)d_in[22];
    const float* w2_b   = (const float*)d_in[23];
    const float* w3_w   = (const float*)d_in[24];
    const float* w3_b   = (const float*)d_in[25];
    const float* wbn1_s = (const float*)d_in[26];
    const float* wbn1_b = (const float*)d_in[27];
    const float* wbn2_s = (const float*)d_in[28];
    const float* wbn2_b = (const float*)d_in[29];
    const float* wbn3_s = (const float*)d_in[30];
    const float* wbn3_b = (const float*)d_in[31];

    float* outp = (float*)d_out;
    float* resB = outp;                 // [B,128,H2,W2]
    float* resA = outp + RESB_ELEMS;    // [B,128,H,W]

    float *A1, *A2, *A3, *B1, *B2, *HT, *WN, *Y;
    cudaGetSymbolAddress((void**)&A1, g_resA1);
    cudaGetSymbolAddress((void**)&A2, g_resA2);
    cudaGetSymbolAddress((void**)&A3, g_resA3);
    cudaGetSymbolAddress((void**)&B1, g_buf1);
    cudaGetSymbolAddress((void**)&B2, g_buf2);
    cudaGetSymbolAddress((void**)&HT, g_hT);
    cudaGetSymbolAddress((void**)&WN, g_wn);
    cudaGetSymbolAddress((void**)&Y,  g_y);

    dim3 cgrid(8, 64, 2);   // (4 px-tiles x 2 oc-halves, rows, batch)
    // ResBlock trunk
    conv_f2_k<64, 3, 1, 1><<<cgrid, 256>>>(x,  c2_w, c2_b, rbn_s,       rbn_b,       A1);
    conv_f2_k<128,3, 2, 2><<<cgrid, 256>>>(A1, c3_w, c3_b, rbn_s + 128, rbn_b + 128, A2);
    conv_f2_k<128,2, 2, 1><<<cgrid, 256>>>(A2, c4_w, c4_b, rbn_s + 256, rbn_b + 256, A3);
    resa_f2_k<<<BB*HWX/128, 256>>>(A1, A2, A3, x, c5_w, c5_b, c1_w, c1_b,
                                   rbn_s + 384, rbn_b + 384, resA);
    // Pointwise MLP (3rd layer writes transposed for the unfold gather)
    gemm128_f2_k<0><<<BB*HWX/128, 256>>>(resA, p_w,          p_b,       pbn_s,       pbn_b,       B1);
    gemm128_f2_k<0><<<BB*HWX/128, 256>>>(B1,   p_w + 16384,  p_b + 128, pbn_s + 128, pbn_b + 128, B2);
    gemm128_f2_k<1><<<BB*HWX/128, 256>>>(B2,   p_w + 32768,  p_b + 256, pbn_s + 256, pbn_b + 256, HT);
    // WeightNet on geometry
    weightnet_k<<<(BB*25*NP2)/256, 256>>>(xyz, w1_w, w1_b, w2_w, w2_b, w3_w, w3_b,
                                          wbn1_s, wbn1_b, wbn2_s, wbn2_b, wbn3_s, wbn3_b, WN);
    // unfold x wn einsum -> y (pixel-major)
    einsum_k<<<BB*NP2/2, 128>>>(HT, WN, Y);
    // final 128x2048 pointwise GEMM -> resB
    final_f2_k<<<BB*NP2/128, 256>>>(Y, lin_w, lin_b, pbn_s + 384, pbn_b + 384, resB);
}

// round 7
// speedup vs baseline: 1.7337x; 1.1231x over previous
#include <cuda_runtime.h>
#include <cstddef>

// ---------------- problem constants ----------------
#define BB   2
#define CINX 64
#define CH   128
#define HH   64
#define WW   1024
#define HWX  (HH*WW)          // 65536
#define H2X  32
#define W2X  512
#define NP2  (H2X*W2X)        // 16384
#define RESB_ELEMS (BB*CH*NP2)   // 4194304

typedef unsigned long long U64;

// f32x2 packed FMA (Blackwell): c = a*b + c elementwise on 2 packed fp32
#define FMA2(c, a, b) asm("fma.rn.f32x2 %0, %1, %2, %0;" : "+l"(c) : "l"(a), "l"(b))
#define PACK2(d, x)   asm("mov.b64 %0, {%1, %1};" : "=l"(d) : "r"(__float_as_uint(x)))
#define UNPK2(lo, hi, d) asm("mov.b64 {%0, %1}, %2;" : "=r"(lo), "=r"(hi) : "l"(d))

// GEMM smem tile geometry: 16 K x 128 px (stride 132), 16 K x 128 oc (stride 132)
#define ROWS 132
#define STAGE_F (16*ROWS*2)    // floats per stage (in + w)

// ---------------- scratch (static device memory; no allocation) ----------------
__device__ float g_resA1[BB*CH*HWX];
__device__ float g_resA2[BB*CH*HWX];
__device__ float g_resA3[BB*CH*HWX];
__device__ float g_buf1 [BB*CH*HWX];
__device__ float g_buf2 [BB*CH*HWX];
__device__ float g_hT   [BB*HWX*CH];          // transposed h: [B][H][W][C]
__device__ float g_wn   [BB*NP2*25*16];       // [B*NP2][25][16]
__device__ float g_y    [(size_t)BB*NP2*2048];// pixel-major: [B*NP2][2048]

__device__ __forceinline__ float lrelu01(float z) { return z > 0.f ? z : 0.01f*z; }

// =====================================================================
// GEMM inner: 16-K chunk, 8 oc x 8 px per thread (pixel-split 4+4), f32x2
// in_s: [16][ROWS] pixel-minor (cols 0..127 used); w_s: [16][ROWS] oc-minor
// pixels: p<4 -> tx*4+p ; p>=4 -> 64+tx*4+(p-4)
// =====================================================================
__device__ __forceinline__ void gemm_chunk_f2(const float* __restrict__ in_s,
                                              const float* __restrict__ w_s,
                                              int ty, int tx, U64 acc[4][8])
{
    #pragma unroll
    for (int kk = 0; kk < 16; kk++) {
        ulonglong2 wa = *reinterpret_cast<const ulonglong2*>(w_s + kk*ROWS + ty*8);
        ulonglong2 wb = *reinterpret_cast<const ulonglong2*>(w_s + kk*ROWS + ty*8 + 4);
        U64 wp[4] = {wa.x, wa.y, wb.x, wb.y};
        float4 xa = *reinterpret_cast<const float4*>(in_s + kk*ROWS + tx*4);
        float4 xb = *reinterpret_cast<const float4*>(in_s + kk*ROWS + 64 + tx*4);
        float xs[8] = {xa.x, xa.y, xa.z, xa.w, xb.x, xb.y, xb.z, xb.w};
        U64 xp[8];
        #pragma unroll
        for (int p = 0; p < 8; p++) PACK2(xp[p], xs[p]);
        #pragma unroll
        for (int j = 0; j < 4; j++)
            #pragma unroll
            for (int p = 0; p < 8; p++)
                FMA2(acc[j][p], wp[j], xp[p]);
    }
}

// =====================================================================
// Direct conv, double-buffered: block = 64 oc x 256 px (one row), CC=4 chans/chunk
// bn(lrelu(conv+b)), f32x2, pixel-split (halves at 0 / 128)
// =====================================================================
template<int CIN, int KS, int DIL, int PAD>
__global__ __launch_bounds__(256)
void conv_f2_k(const float* __restrict__ in, const float* __restrict__ wg,
               const float* __restrict__ bias, const float* __restrict__ bns,
               const float* __restrict__ bnb, float* __restrict__ out)
{
    constexpr int CC = 4, WT = 256, KK = KS*KS, IWP = 260;
    constexpr int INTOT = CC*KS*IWP;
    constexpr int NIN   = (INTOT + 255)/256;
    constexpr int WROW  = 68;
    constexpr int WTOT  = CC*KK*WROW;
    constexpr int WELEM = 64*CC*KK;
    constexpr int NW    = (WELEM + 1023)/1024;
    constexpr int WPO   = CC*KK;
    constexpr int NCH   = CIN/CC;

    __shared__ __align__(16) float in_s[2][INTOT];
    __shared__ __align__(16) float w_s[2][WTOT];

    const int bx  = blockIdx.x;
    const int w0  = (bx >> 1) * WT;
    const int oc0 = (bx & 1) * 64;
    const int h   = blockIdx.y;
    const int b   = blockIdx.z;
    const int tid = threadIdx.x;
    const int ty = tid >> 5, tx = tid & 31;

    U64 acc[4][8];
    #pragma unroll
    for (int j = 0; j < 4; j++)
        #pragma unroll
        for (int p = 0; p < 8; p++) acc[j][p] = 0ULL;

    float  rin[NIN];
    float4 rw[NW];

    auto load_chunk = [&](int cb) {
        #pragma unroll
        for (int j = 0; j < NIN; j++) {
            int idx = tid + j*256;
            float v = 0.f;
            if (idx < INTOT) {
                int ci  = idx / (KS*IWP);
                int rem = idx - ci*(KS*IWP);
                int r = rem / IWP, col = rem - r*IWP;
                int gy = h - PAD + r*DIL;
                int gx = w0 - PAD + col;
                if ((unsigned)gy < (unsigned)HH && (unsigned)gx < (unsigned)WW)
                    v = in[((b*CIN + cb + ci)*HH + gy)*WW + gx];
            }
            rin[j] = v;
        }
        #pragma unroll
        for (int j = 0; j < NW; j++) {
            int idx = tid*4 + j*1024;
            if (idx < WELEM) {
                int ocl = idx / WPO;
                int r   = idx - ocl*WPO;
                rw[j] = *reinterpret_cast<const float4*>(&wg[((oc0 + ocl)*CIN + cb)*KK + r]);
            }
        }
    };
    auto store_stage = [&](int st) {
        #pragma unroll
        for (int j = 0; j < NIN; j++) {
            int idx = tid + j*256;
            if (idx < INTOT) in_s[st][idx] = rin[j];
        }
        #pragma unroll
        for (int j = 0; j < NW; j++) {
            int idx = tid*4 + j*1024;
            if (idx < WELEM) {
                int ocl = idx / WPO;
                int r   = idx - ocl*WPO;
                float vv[4] = {rw[j].x, rw[j].y, rw[j].z, rw[j].w};
                #pragma unroll
                for (int jj = 0; jj < 4; jj++)
                    w_s[st][(r + jj)*WROW + ocl] = vv[jj];
            }
        }
    };

    load_chunk(0);
    store_stage(0);
    if (NCH > 1) load_chunk(CC);
    __syncthreads();

    for (int c = 0; c < NCH; c++) {
        if (c + 1 < NCH) store_stage((c + 1) & 1);
        if (c + 2 < NCH) load_chunk((c + 2)*CC);
        const int st = c & 1;
        #pragma unroll
        for (int ci = 0; ci < CC; ci++) {
            #pragma unroll
            for (int kh = 0; kh < KS; kh++) {
                const float* xrow = &in_s[st][(ci*KS + kh)*IWP];
                float xr1[8], xr2[8];
                *reinterpret_cast<float4*>(&xr1[0]) = *reinterpret_cast<const float4*>(xrow + tx*4);
                *reinterpret_cast<float4*>(&xr1[4]) = *reinterpret_cast<const float4*>(xrow + tx*4 + 4);
                *reinterpret_cast<float4*>(&xr2[0]) = *reinterpret_cast<const float4*>(xrow + 128 + tx*4);
                *reinterpret_cast<float4*>(&xr2[4]) = *reinterpret_cast<const float4*>(xrow + 128 + tx*4 + 4);
                #pragma unroll
                for (int kw = 0; kw < KS; kw++) {
                    const float* wrow = &w_s[st][(ci*KK + kh*KS + kw)*WROW + ty*8];
                    ulonglong2 wa = *reinterpret_cast<const ulonglong2*>(wrow);
                    ulonglong2 wb = *reinterpret_cast<const ulonglong2*>(wrow + 4);
                    U64 wp[4] = {wa.x, wa.y, wb.x, wb.y};
                    U64 xp[8];
                    #pragma unroll
                    for (int p = 0; p < 4; p++) PACK2(xp[p], xr1[p + kw*DIL]);
                    #pragma unroll
                    for (int p = 4; p < 8; p++) PACK2(xp[p], xr2[p - 4 + kw*DIL]);
                    #pragma unroll
                    for (int j = 0; j < 4; j++)
                        #pragma unroll
                        for (int p = 0; p < 8; p++)
                            FMA2(acc[j][p], wp[j], xp[p]);
                }
            }
        }
        __syncthreads();
    }
    #pragma unroll
    for (int j = 0; j < 4; j++) {
        float lo[8], hi[8];
        #pragma unroll
        for (int p = 0; p < 8; p++) {
            unsigned a, c; UNPK2(a, c, acc[j][p]);
            lo[p] = __uint_as_float(a); hi[p] = __uint_as_float(c);
        }
        #pragma unroll
        for (int hh2 = 0; hh2 < 2; hh2++) {
            int oc = oc0 + ty*8 + 2*j + hh2;
            const float* src = hh2 ? hi : lo;
            float bi = bias[oc], s = bns[oc], bb2 = bnb[oc];
            float zt[8];
            #pragma unroll
            for (int p = 0; p < 8; p++) zt[p] = s*lrelu01(src[p] + bi) + bb2;
            float* op = &out[((b*128 + oc)*HH + h)*WW + w0];
            *reinterpret_cast<float4*>(op + tx*4)       = make_float4(zt[0], zt[1], zt[2], zt[3]);
            *reinterpret_cast<float4*>(op + 128 + tx*4) = make_float4(zt[4], zt[5], zt[6], zt[7]);
        }
    }
}

// =====================================================================
// Pointwise 128->128, double-buffered, NCHW in, relu(bn(Wx+b)).
// TR=1 writes transposed [pix][C]. 128 px per block.
// =====================================================================
template<int TR>
__global__ __launch_bounds__(256, 2)
void gemm128_f2_k(const float* __restrict__ in, const float* __restrict__ wg,
                  const float* __restrict__ bias, const float* __restrict__ bns,
                  const float* __restrict__ bnb, float* __restrict__ out)
{
    __shared__ __align__(16) float sraw[2*STAGE_F];
    const int gp = blockIdx.x * 128;
    const int b = gp / HWX, pp = gp - b*HWX;
    const int tid = threadIdx.x, ty = tid >> 4, tx = tid & 15;
    const int oc1 = tid >> 2, q1 = tid & 3;
    U64 acc[4][8];
    #pragma unroll
    for (int j = 0; j < 4; j++)
        #pragma unroll
        for (int p = 0; p < 8; p++) acc[j][p] = 0ULL;

    float4 ra, rb, rwa, rwb;
    auto load_chunk = [&](int kc) {
        const float* sp = &in[((b*128 + kc*16 + ty)*HWX) + pp + tx*8];
        ra = *reinterpret_cast<const float4*>(sp);
        rb = *reinterpret_cast<const float4*>(sp + 4);
        rwa = *reinterpret_cast<const float4*>(&wg[oc1*128 + kc*16 + q1*4]);
        rwb = *reinterpret_cast<const float4*>(&wg[(oc1 + 64)*128 + kc*16 + q1*4]);
    };
    auto store_stage = [&](int st) {
        float* in_s = sraw + st*STAGE_F;
        float* w_s  = in_s + 16*ROWS;
        *reinterpret_cast<float4*>(&in_s[ty*ROWS + tx*8])     = ra;
        *reinterpret_cast<float4*>(&in_s[ty*ROWS + tx*8 + 4]) = rb;
        w_s[(q1*4+0)*ROWS + oc1] = rwa.x; w_s[(q1*4+1)*ROWS + oc1] = rwa.y;
        w_s[(q1*4+2)*ROWS + oc1] = rwa.z; w_s[(q1*4+3)*ROWS + oc1] = rwa.w;
        w_s[(q1*4+0)*ROWS + oc1+64] = rwb.x; w_s[(q1*4+1)*ROWS + oc1+64] = rwb.y;
        w_s[(q1*4+2)*ROWS + oc1+64] = rwb.z; w_s[(q1*4+3)*ROWS + oc1+64] = rwb.w;
    };

    load_chunk(0); store_stage(0);
    load_chunk(1);
    __syncthreads();
    for (int kc = 0; kc < 8; kc++) {
        if (kc + 1 < 8) store_stage((kc + 1) & 1);
        if (kc + 2 < 8) load_chunk(kc + 2);
        const float* base = sraw + (kc & 1)*STAGE_F;
        gemm_chunk_f2(base, base + 16*ROWS, ty, tx, acc);
        __syncthreads();
    }

    if (TR == 0) {
        #pragma unroll
        for (int j = 0; j < 4; j++) {
            float lo[8], hi[8];
            #pragma unroll
            for (int p = 0; p < 8; p++) {
                unsigned a, c; UNPK2(a, c, acc[j][p]);
                lo[p] = __uint_as_float(a); hi[p] = __uint_as_float(c);
            }
            #pragma unroll
            for (int hh2 = 0; hh2 < 2; hh2++) {
                int oc = ty*8 + 2*j + hh2;
                const float* src = hh2 ? hi : lo;
                float bi = bias[oc], s = bns[oc], bb2 = bnb[oc];
                float zt[8];
                #pragma unroll
                for (int p = 0; p < 8; p++) {
                    float z = s*(src[p] + bi) + bb2;
                    zt[p] = z > 0.f ? z : 0.f;
                }
                float* op = &out[((b*128 + oc)*HWX) + pp];
                *reinterpret_cast<float4*>(op + tx*4)      = make_float4(zt[0], zt[1], zt[2], zt[3]);
                *reinterpret_cast<float4*>(op + 64 + tx*4) = make_float4(zt[4], zt[5], zt[6], zt[7]);
            }
        }
    } else {
        // 4-pass transpose via smem staging (reuses sraw; needs 32*129 floats)
        float* stage = sraw;
        for (int g = 0; g < 4; g++) {
            __syncthreads();
            if ((ty >> 2) == g) {
                #pragma unroll
                for (int j = 0; j < 4; j++) {
                    unsigned a, c;
                    float lo[8], hi[8];
                    #pragma unroll
                    for (int p = 0; p < 8; p++) {
                        UNPK2(a, c, acc[j][p]);
                        lo[p] = __uint_as_float(a); hi[p] = __uint_as_float(c);
                    }
                    int oc = ty*8 + 2*j;
                    int ocl = oc - g*32;
                    float bi0 = bias[oc],   s0 = bns[oc],   b0 = bnb[oc];
                    float bi1 = bias[oc+1], s1 = bns[oc+1], b1 = bnb[oc+1];
                    #pragma unroll
                    for (int p = 0; p < 8; p++) {
                        int col = (p < 4) ? (tx*4 + p) : (64 + tx*4 + p - 4);
                        float z0 = s0*(lo[p] + bi0) + b0;
                        float z1 = s1*(hi[p] + bi1) + b1;
                        stage[ocl*129 + col]     = z0 > 0.f ? z0 : 0.f;
                        stage[(ocl+1)*129 + col] = z1 > 0.f ? z1 : 0.f;
                    }
                }
            }
            __syncthreads();
            for (int t2 = tid; t2 < 1024; t2 += 256) {
                int pix = t2 >> 3, c4 = t2 & 7;
                float4 v;
                v.x = stage[(c4*4+0)*129 + pix];
                v.y = stage[(c4*4+1)*129 + pix];
                v.z = stage[(c4*4+2)*129 + pix];
                v.w = stage[(c4*4+3)*129 + pix];
                *reinterpret_cast<float4*>(&out[(size_t)(b*HWX + pp + pix)*128 + g*32 + c4*4]) = v;
            }
        }
    }
}

// =====================================================================
// resA: bn3(lrelu(c5 @ concat + c5_b)) + lrelu(c1 @ x + c1_b), double-buffered
// =====================================================================
__global__ __launch_bounds__(256)
void resa_f2_k(const float* __restrict__ r1, const float* __restrict__ r2,
               const float* __restrict__ r3, const float* __restrict__ x,
               const float* __restrict__ c5w, const float* __restrict__ c5b,
               const float* __restrict__ c1w, const float* __restrict__ c1b,
               const float* __restrict__ bns, const float* __restrict__ bnb,
               float* __restrict__ out)
{
    __shared__ __align__(16) float sraw[2*STAGE_F];
    const int gp = blockIdx.x * 128;
    const int b = gp / HWX, pp = gp - b*HWX;
    const int tid = threadIdx.x, ty = tid >> 4, tx = tid & 15;
    const int oc1 = tid >> 2, q1 = tid & 3;
    U64 acc[4][8], acc2[4][8];
    #pragma unroll
    for (int j = 0; j < 4; j++)
        #pragma unroll
        for (int p = 0; p < 8; p++) { acc[j][p] = 0ULL; acc2[j][p] = 0ULL; }

    float4 ra, rb, rwa, rwb;
    auto load_c = [&](int c) {
        if (c < 24) {
            const float* src = c < 8 ? r1 : (c < 16 ? r2 : r3);
            int chb = (c & 7)*16;
            const float* sp = &src[((b*128 + chb + ty)*HWX) + pp + tx*8];
            ra = *reinterpret_cast<const float4*>(sp);
            rb = *reinterpret_cast<const float4*>(sp + 4);
            rwa = *reinterpret_cast<const float4*>(&c5w[oc1*384 + c*16 + q1*4]);
            rwb = *reinterpret_cast<const float4*>(&c5w[(oc1 + 64)*384 + c*16 + q1*4]);
        } else {
            int kc = c - 24;
            const float* sp = &x[((b*64 + kc*16 + ty)*HWX) + pp + tx*8];
            ra = *reinterpret_cast<const float4*>(sp);
            rb = *reinterpret_cast<const float4*>(sp + 4);
            rwa = *reinterpret_cast<const float4*>(&c1w[oc1*64 + kc*16 + q1*4]);
            rwb = *reinterpret_cast<const float4*>(&c1w[(oc1 + 64)*64 + kc*16 + q1*4]);
        }
    };
    auto store_stage = [&](int st) {
        float* in_s = sraw + st*STAGE_F;
        float* w_s  = in_s + 16*ROWS;
        *reinterpret_cast<float4*>(&in_s[ty*ROWS + tx*8])     = ra;
        *reinterpret_cast<float4*>(&in_s[ty*ROWS + tx*8 + 4]) = rb;
        w_s[(q1*4+0)*ROWS + oc1] = rwa.x; w_s[(q1*4+1)*ROWS + oc1] = rwa.y;
        w_s[(q1*4+2)*ROWS + oc1] = rwa.z; w_s[(q1*4+3)*ROWS + oc1] = rwa.w;
        w_s[(q1*4+0)*ROWS + oc1+64] = rwb.x; w_s[(q1*4+1)*ROWS + oc1+64] = rwb.y;
        w_s[(q1*4+2)*ROWS + oc1+64] = rwb.z; w_s[(q1*4+3)*ROWS + oc1+64] = rwb.w;
    };

    load_c(0); store_stage(0);
    load_c(1);
    __syncthreads();
    for (int c = 0; c < 28; c++) {
        if (c + 1 < 28) store_stage((c + 1) & 1);
        if (c + 2 < 28) load_c(c + 2);
        const float* base = sraw + (c & 1)*STAGE_F;
        if (c < 24) gemm_chunk_f2(base, base + 16*ROWS, ty, tx, acc);
        else        gemm_chunk_f2(base, base + 16*ROWS, ty, tx, acc2);
        __syncthreads();
    }

    #pragma unroll
    for (int j = 0; j < 4; j++) {
        float lo[8], hi[8], lo2[8], hi2[8];
        #pragma unroll
        for (int p = 0; p < 8; p++) {
            unsigned a, c; UNPK2(a, c, acc[j][p]);
            lo[p] = __uint_as_float(a); hi[p] = __uint_as_float(c);
            UNPK2(a, c, acc2[j][p]);
            lo2[p] = __uint_as_float(a); hi2[p] = __uint_as_float(c);
        }
        #pragma unroll
        for (int hh2 = 0; hh2 < 2; hh2++) {
            int oc = ty*8 + 2*j + hh2;
            const float* m  = hh2 ? hi  : lo;
            const float* m2 = hh2 ? hi2 : lo2;
            float b5 = c5b[oc], b1 = c1b[oc], s = bns[oc], bb2 = bnb[oc];
            float zt[8];
            #pragma unroll
            for (int p = 0; p < 8; p++)
                zt[p] = s*lrelu01(m[p] + b5) + bb2 + lrelu01(m2[p] + b1);
            float* op = &out[((b*128 + oc)*HWX) + pp];
            *reinterpret_cast<float4*>(op + tx*4)      = make_float4(zt[0], zt[1], zt[2], zt[3]);
            *reinterpret_cast<float4*>(op + 64 + tx*4) = make_float4(zt[4], zt[5], zt[6], zt[7]);
        }
    }
}

// =====================================================================
// WeightNet: gxyz -> 8 -> 8 -> 16, per (b, k, pixel)
// =====================================================================
__global__ __launch_bounds__(256)
void weightnet_k(const float* __restrict__ xyz,
                 const float* __restrict__ w1w, const float* __restrict__ w1b,
                 const float* __restrict__ w2w, const float* __restrict__ w2b,
                 const float* __restrict__ w3w, const float* __restrict__ w3b,
                 const float* __restrict__ s1, const float* __restrict__ b1,
                 const float* __restrict__ s2, const float* __restrict__ b2,
                 const float* __restrict__ s3, const float* __restrict__ b3,
                 float* __restrict__ out)
{
    int g = blockIdx.x*256 + threadIdx.x;   // B*25*NP2 = 819200
    int pix = g & (NP2 - 1);
    int rest = g >> 14;
    int k = rest % 25, b = rest / 25;
    int h2 = pix >> 9, w2 = pix & 511;
    int hi = 2*h2 - 2 + k/5, wi = 2*w2 - 2 + (k % 5);
    bool inb = ((unsigned)hi < (unsigned)HH) && ((unsigned)wi < (unsigned)WW);
    float gv[3];
    #pragma unroll
    for (int c = 0; c < 3; c++) {
        float ctr = xyz[(b*3 + c)*HWX + (2*h2)*WW + 2*w2];
        float nb  = inb ? xyz[(b*3 + c)*HWX + hi*WW + wi] : 0.f;
        gv[c] = nb - ctr;
    }
    float a1[8];
    #pragma unroll
    for (int j = 0; j < 8; j++) {
        float z = w1b[j];
        #pragma unroll
        for (int c = 0; c < 3; c++) z += w1w[j*3 + c]*gv[c];
        z = s1[j]*z + b1[j];
        a1[j] = z > 0.f ? z : 0.f;
    }
    float a2[8];
    #pragma unroll
    for (int j = 0; j < 8; j++) {
        float z = w2b[j];
        #pragma unroll
        for (int i = 0; i < 8; i++) z += w2w[j*8 + i]*a1[i];
        z = s2[j]*z + b2[j];
        a2[j] = z > 0.f ? z : 0.f;
    }
    float o[16];
    #pragma unroll
    for (int n = 0; n < 16; n++) {
        float z = w3b[n];
        #pragma unroll
        for (int i = 0; i < 8; i++) z += w3w[n*8 + i]*a2[i];
        z = s3[n]*z + b3[n];
        o[n] = z > 0.f ? z : 0.f;
    }
    size_t base = (((size_t)(b*NP2 + pix))*25 + k)*16;
    #pragma unroll
    for (int q = 0; q < 4; q++)
        *reinterpret_cast<float4*>(&out[base + q*4]) =
            make_float4(o[q*4], o[q*4+1], o[q*4+2], o[q*4+3]);
}

// =====================================================================
// Einsum: y[pix][c*16+n] = sum_k unf(hT)[c][k] * wn[pix][k][n], 2 pixels/block
// u_s relayout [pl][k][c] + pixel-split c tile -> conflict-free LDS.128
// =====================================================================
__global__ __launch_bounds__(128)
void einsum_k(const float* __restrict__ hT, const float* __restrict__ wn,
              float* __restrict__ y)
{
    __shared__ __align__(16) float u_s[2][25][128];
    __shared__ float wn_s[2][400];
    const int gpix = blockIdx.x*2;
    const int b = gpix / NP2;
    const int tid = threadIdx.x;

    for (int i = tid; i < 800; i += 128) {
        int pl = i / 400, r = i - pl*400;
        wn_s[pl][r] = wn[(size_t)(gpix + pl)*400 + r];
    }
    for (int idx = 0; idx < 50; idx++) {
        int pl = idx / 25, k = idx - pl*25;
        int pp = (gpix + pl) - b*NP2;
        int h2 = pp >> 9, w2 = pp & 511;
        int hi = 2*h2 - 2 + k/5, wi = 2*w2 - 2 + (k % 5);
        float v = 0.f;
        if ((unsigned)hi < (unsigned)HH && (unsigned)wi < (unsigned)WW)
            v = hT[((size_t)(b*HH + hi)*WW + wi)*128 + tid];
        u_s[pl][k][tid] = v;
    }
    __syncthreads();

    const int s = tid & 63, pl = tid >> 6;
    const int cg = s & 15, ng = s >> 4;
    float acc[8][4];
    #pragma unroll
    for (int i = 0; i < 8; i++)
        #pragma unroll
        for (int n = 0; n < 4; n++) acc[i][n] = 0.f;

    #pragma unroll
    for (int k = 0; k < 25; k++) {
        float4 ua = *reinterpret_cast<const float4*>(&u_s[pl][k][cg*4]);
        float4 ub = *reinterpret_cast<const float4*>(&u_s[pl][k][64 + cg*4]);
        float u[8] = {ua.x, ua.y, ua.z, ua.w, ub.x, ub.y, ub.z, ub.w};
        float4 wv = *reinterpret_cast<const float4*>(&wn_s[pl][k*16 + ng*4]);
        float wvv[4] = {wv.x, wv.y, wv.z, wv.w};
        #pragma unroll
        for (int i = 0; i < 8; i++)
            #pragma unroll
            for (int n = 0; n < 4; n++) acc[i][n] += u[i]*wvv[n];
    }
    size_t base = (size_t)(gpix + pl)*2048;
    #pragma unroll
    for (int i = 0; i < 8; i++) {
        int c = (i < 4) ? (cg*4 + i) : (64 + cg*4 + i - 4);
        *reinterpret_cast<float4*>(&y[base + c*16 + ng*4]) =
            make_float4(acc[i][0], acc[i][1], acc[i][2], acc[i][3]);
    }
}

// =====================================================================
// Final GEMM: K=2048, y pixel-major in, resB NCHW out, relu(bn(.)), double-buffered
// =====================================================================
__global__ __launch_bounds__(256, 2)
void final_f2_k(const float* __restrict__ y, const float* __restrict__ lw,
                const float* __restrict__ lb, const float* __restrict__ bns,
                const float* __restrict__ bnb, float* __restrict__ out)
{
    __shared__ __align__(16) float sraw[2*STAGE_F];
    const int gp = blockIdx.x * 128;          // over B*NP2
    const int b = gp / NP2, pp = gp - b*NP2;
    const int tid = threadIdx.x, ty = tid >> 4, tx = tid & 15;
    const int oc1 = tid >> 2, q1 = tid & 3;
    U64 acc[4][8];
    #pragma unroll
    for (int j = 0; j < 4; j++)
        #pragma unroll
        for (int p = 0; p < 8; p++) acc[j][p] = 0ULL;

    float4 ra, rb, rwa, rwb;
    auto load_chunk = [&](int kc) {
        ra  = *reinterpret_cast<const float4*>(&y[(size_t)(gp + oc1)*2048 + kc*16 + q1*4]);
        rb  = *reinterpret_cast<const float4*>(&y[(size_t)(gp + oc1 + 64)*2048 + kc*16 + q1*4]);
        rwa = *reinterpret_cast<const float4*>(&lw[oc1*2048 + kc*16 + q1*4]);
        rwb = *reinterpret_cast<const float4*>(&lw[(oc1 + 64)*2048 + kc*16 + q1*4]);
    };
    auto store_stage = [&](int st) {
        float* in_s = sraw + st*STAGE_F;
        float* w_s  = in_s + 16*ROWS;
        in_s[(q1*4+0)*ROWS + oc1] = ra.x; in_s[(q1*4+1)*ROWS + oc1] = ra.y;
        in_s[(q1*4+2)*ROWS + oc1] = ra.z; in_s[(q1*4+3)*ROWS + oc1] = ra.w;
        in_s[(q1*4+0)*ROWS + oc1+64] = rb.x; in_s[(q1*4+1)*ROWS + oc1+64] = rb.y;
        in_s[(q1*4+2)*ROWS + oc1+64] = rb.z; in_s[(q1*4+3)*ROWS + oc1+64] = rb.w;
        w_s[(q1*4+0)*ROWS + oc1] = rwa.x; w_s[(q1*4+1)*ROWS + oc1] = rwa.y;
        w_s[(q1*4+2)*ROWS + oc1] = rwa.z; w_s[(q1*4+3)*ROWS + oc1] = rwa.w;
        w_s[(q1*4+0)*ROWS + oc1+64] = rwb.x; w_s[(q1*4+1)*ROWS + oc1+64] = rwb.y;
        w_s[(q1*4+2)*ROWS + oc1+64] = rwb.z; w_s[(q1*4+3)*ROWS + oc1+64] = rwb.w;
    };

    load_chunk(0); store_stage(0);
    load_chunk(1);
    __syncthreads();
    for (int kc = 0; kc < 128; kc++) {
        if (kc + 1 < 128) store_stage((kc + 1) & 1);
        if (kc + 2 < 128) load_chunk(kc + 2);
        const float* base = sraw + (kc & 1)*STAGE_F;
        gemm_chunk_f2(base, base + 16*ROWS, ty, tx, acc);
        __syncthreads();
    }
    #pragma unroll
    for (int j = 0; j < 4; j++) {
        float lo[8], hi[8];
        #pragma unroll
        for (int p = 0; p < 8; p++) {
            unsigned a, c; UNPK2(a, c, acc[j][p]);
            lo[p] = __uint_as_float(a); hi[p] = __uint_as_float(c);
        }
        #pragma unroll
        for (int hh2 = 0; hh2 < 2; hh2++) {
            int oc = ty*8 + 2*j + hh2;
            const float* src = hh2 ? hi : lo;
            float bi = lb[oc], s = bns[oc], bb2 = bnb[oc];
            float zt[8];
            #pragma unroll
            for (int p = 0; p < 8; p++) {
                float z = s*(src[p] + bi) + bb2;
                zt[p] = z > 0.f ? z : 0.f;
            }
            float* op = &out[((b*128 + oc)*NP2) + pp];
            *reinterpret_cast<float4*>(op + tx*4)      = make_float4(zt[0], zt[1], zt[2], zt[3]);
            *reinterpret_cast<float4*>(op + 64 + tx*4) = make_float4(zt[4], zt[5], zt[6], zt[7]);
        }
    }
}

// =====================================================================
// host launcher
// =====================================================================
extern "C" void kernel_launch(void* const* d_in, const int* in_sizes, int n_in,
                              void* d_out, int out_size)
{
    const float* x      = (const float*)d_in[0];
    const float* xyz    = (const float*)d_in[1];
    const float* c1_w   = (const float*)d_in[2];
    const float* c1_b   = (const float*)d_in[3];
    const float* c2_w   = (const float*)d_in[4];
    const float* c2_b   = (const float*)d_in[5];
    const float* c3_w   = (const float*)d_in[6];
    const float* c3_b   = (const float*)d_in[7];
    const float* c4_w   = (const float*)d_in[8];
    const float* c4_b   = (const float*)d_in[9];
    const float* c5_w   = (const float*)d_in[10];
    const float* c5_b   = (const float*)d_in[11];
    const float* rbn_s  = (const float*)d_in[12];
    const float* rbn_b  = (const float*)d_in[13];
    const float* p_w    = (const float*)d_in[14];
    const float* p_b    = (const float*)d_in[15];
    const float* pbn_s  = (const float*)d_in[16];
    const float* pbn_b  = (const float*)d_in[17];
    const float* lin_w  = (const float*)d_in[18];
    const float* lin_b  = (const float*)d_in[19];
    const float* w1_w   = (const float*)d_in[20];
    const float* w1_b   = (const float*)d_in[21];
    const float* w2_w   = (const float*)d_in[22];
    const float* w2_b   = (const float*)d_in[23];
    const float* w3_w   = (const float*)d_in[24];
    const float* w3_b   = (const float*)d_in[25];
    const float* wbn1_s = (const float*)d_in[26];
    const float* wbn1_b = (const float*)d_in[27];
    const float* wbn2_s = (const float*)d_in[28];
    const float* wbn2_b = (const float*)d_in[29];
    const float* wbn3_s = (const float*)d_in[30];
    const float* wbn3_b = (const float*)d_in[31];

    float* outp = (float*)d_out;
    float* resB = outp;                 // [B,128,H2,W2]
    float* resA = outp + RESB_ELEMS;    // [B,128,H,W]

    float *A1, *A2, *A3, *B1, *B2, *HT, *WN, *Y;
    cudaGetSymbolAddress((void**)&A1, g_resA1);
    cudaGetSymbolAddress((void**)&A2, g_resA2);
    cudaGetSymbolAddress((void**)&A3, g_resA3);
    cudaGetSymbolAddress((void**)&B1, g_buf1);
    cudaGetSymbolAddress((void**)&B2, g_buf2);
    cudaGetSymbolAddress((void**)&HT, g_hT);
    cudaGetSymbolAddress((void**)&WN, g_wn);
    cudaGetSymbolAddress((void**)&Y,  g_y);

    dim3 cgrid(8, 64, 2);   // (4 px-tiles x 2 oc-halves, rows, batch)
    // ResBlock trunk
    conv_f2_k<64, 3, 1, 1><<<cgrid, 256>>>(x,  c2_w, c2_b, rbn_s,       rbn_b,       A1);
    conv_f2_k<128,3, 2, 2><<<cgrid, 256>>>(A1, c3_w, c3_b, rbn_s + 128, rbn_b + 128, A2);
    conv_f2_k<128,2, 2, 1><<<cgrid, 256>>>(A2, c4_w, c4_b, rbn_s + 256, rbn_b + 256, A3);
    resa_f2_k<<<BB*HWX/128, 256>>>(A1, A2, A3, x, c5_w, c5_b, c1_w, c1_b,
                                   rbn_s + 384, rbn_b + 384, resA);
    // Pointwise MLP (3rd layer writes transposed for the unfold gather)
    gemm128_f2_k<0><<<BB*HWX/128, 256>>>(resA, p_w,          p_b,       pbn_s,       pbn_b,       B1);
    gemm128_f2_k<0><<<BB*HWX/128, 256>>>(B1,   p_w + 16384,  p_b + 128, pbn_s + 128, pbn_b + 128, B2);
    gemm128_f2_k<1><<<BB*HWX/128, 256>>>(B2,   p_w + 32768,  p_b + 256, pbn_s + 256, pbn_b + 256, HT);
    // WeightNet on geometry
    weightnet_k<<<(BB*25*NP2)/256, 256>>>(xyz, w1_w, w1_b, w2_w, w2_b, w3_w, w3_b,
                                          wbn1_s, wbn1_b, wbn2_s, wbn2_b, wbn3_s, wbn3_b, WN);
    // unfold x wn einsum -> y (pixel-major)
    einsum_k<<<BB*NP2/2, 128>>>(HT, WN, Y);
    // final 128x2048 pointwise GEMM -> resB
    final_f2_k<<<BB*NP2/128, 256>>>(Y, lin_w, lin_b, pbn_s + 384, pbn_b + 384, resB);
}